// round 1
// baseline (speedup 1.0000x reference)
#include <cuda_runtime.h>
#include <math.h>

// ---------------- problem constants ----------------
#define BG     32
#define NPG    1024
#define DEGC   8
#define F_IN   512
#define HD     1024
#define OUTD   10
#define E_TOT  (BG*NPG*DEGC)   // 262144
#define N1     (BG*NPG)        // 32768
#define KP1    512
#define N2     (BG*KP1)        // 16384
#define KP2    256
#define N3     (BG*KP2)        // 8192
#define FC1D   512
#define BN_EPS 1e-5f

// ---------------- scratch layout (floats) ----------------
#define F_LIN1   ((size_t)0)
#define F_AGG1   (F_LIN1 + (size_t)N1*HD)
#define F_HP1    (F_AGG1 + (size_t)N1*HD)
#define F_LIN2   (F_HP1  + (size_t)N2*HD)
#define F_AGG2   (F_LIN2 + (size_t)N2*HD)
#define F_HP2    (F_AGG2 + (size_t)N2*HD)
#define F_NORM1  (F_HP2  + (size_t)N3*HD)
#define F_NORM2  (F_NORM1 + E_TOT)
#define F_DEG1   (F_NORM2 + E_TOT)
#define F_DINV1  (F_DEG1 + N1)
#define F_DEG2   (F_DINV1 + N1)
#define F_DINV2  (F_DEG2 + N2)
#define F_SCORE1 (F_DINV2 + N2)
#define F_SCORE2 (F_SCORE1 + N1)
#define F_VAL1   (F_SCORE2 + N2)
#define F_VAL2   (F_VAL1 + N2)
#define F_COLSUM (F_VAL2 + N3)
#define F_COLSQ  (F_COLSUM + HD)
#define F_SCALE  (F_COLSQ + HD)
#define F_SHIFT  (F_SCALE + HD)
#define F_PN     (F_SHIFT + HD)
#define F_X1     (F_PN + HD)
#define F_X2     (F_X1 + BG*HD)
#define F_Z      (F_X2 + BG*HD)
#define F_END    (F_Z + BG*FC1D)

#define I_SRC2   ((size_t)0)
#define I_DST2   (I_SRC2 + E_TOT)
#define I_PERM1  (I_DST2 + E_TOT)
#define I_PERM2  (I_PERM1 + N2)
#define I_NEWID  (I_PERM2 + N3)
#define I_END    (I_NEWID + N1)

__device__ float d_fscratch[F_END];
__device__ int   d_iscratch[I_END];

// ---------------- SGEMM 128x128x16, 8x8 per thread ----------------
__global__ __launch_bounds__(256) void sgemm_k(
    const float* __restrict__ A, const float* __restrict__ B,
    float* __restrict__ C, int M, int N, int K)
{
    __shared__ float As[16][128];
    __shared__ float Bs[16][128];
    const int tid = threadIdx.x;
    const int bm = blockIdx.y * 128;
    const int bn = blockIdx.x * 128;
    const int tcol = tid & 15;       // 0..15
    const int trow = tid >> 4;       // 0..15

    float acc[8][8];
    #pragma unroll
    for (int i = 0; i < 8; i++)
        #pragma unroll
        for (int j = 0; j < 8; j++) acc[i][j] = 0.f;

    for (int kk = 0; kk < K; kk += 16) {
        // load A tile: 128x16
        #pragma unroll
        for (int i = 0; i < 2; i++) {
            int r = (tid >> 2) + i * 64;
            int c = (tid & 3) * 4;
            float4 v = *(const float4*)&A[(size_t)(bm + r) * K + kk + c];
            As[c + 0][r] = v.x; As[c + 1][r] = v.y;
            As[c + 2][r] = v.z; As[c + 3][r] = v.w;
        }
        // load B tile: 16x128
        #pragma unroll
        for (int i = 0; i < 2; i++) {
            int r = (tid >> 5) + i * 8;
            int c = (tid & 31) * 4;
            *(float4*)&Bs[r][c] = *(const float4*)&B[(size_t)(kk + r) * N + bn + c];
        }
        __syncthreads();
        #pragma unroll
        for (int k = 0; k < 16; k++) {
            float a[8], b[8];
            #pragma unroll
            for (int i = 0; i < 8; i++) a[i] = As[k][trow * 8 + i];
            #pragma unroll
            for (int j = 0; j < 8; j++) b[j] = Bs[k][tcol * 8 + j];
            #pragma unroll
            for (int i = 0; i < 8; i++)
                #pragma unroll
                for (int j = 0; j < 8; j++) acc[i][j] += a[i] * b[j];
        }
        __syncthreads();
    }
    #pragma unroll
    for (int i = 0; i < 8; i++) {
        #pragma unroll
        for (int j = 0; j < 8; j += 4) {
            float4 v = make_float4(acc[i][j], acc[i][j+1], acc[i][j+2], acc[i][j+3]);
            *(float4*)&C[(size_t)(bm + trow * 8 + i) * N + bn + tcol * 8 + j] = v;
        }
    }
}

// ---------------- small kernels ----------------
__global__ void fill_k(float* p, int n, float v) {
    int i = blockIdx.x * blockDim.x + threadIdx.x;
    if (i < n) p[i] = v;
}

__global__ void degcount1_k(const int* __restrict__ dst, float* deg, int n) {
    int e = blockIdx.x * blockDim.x + threadIdx.x;
    if (e < n) atomicAdd(&deg[dst[e]], 1.0f);
}

__global__ void degcount2_k(const int* __restrict__ src2, const int* __restrict__ dst2,
                            float* deg, int n) {
    int e = blockIdx.x * blockDim.x + threadIdx.x;
    if (e < n && src2[e] >= 0) atomicAdd(&deg[dst2[e]], 1.0f);
}

__global__ void dinv_k(const float* __restrict__ deg, float* __restrict__ dinv, int n) {
    int i = blockIdx.x * blockDim.x + threadIdx.x;
    if (i < n) dinv[i] = rsqrtf(deg[i]);
}

__global__ void norm1_k(const int* __restrict__ src, const int* __restrict__ dst,
                        const float* __restrict__ dinv, float* __restrict__ nrm, int n) {
    int e = blockIdx.x * blockDim.x + threadIdx.x;
    if (e < n) nrm[e] = dinv[src[e]] * dinv[dst[e]];
}

__global__ void norm2_k(const int* __restrict__ src2, const int* __restrict__ dst2,
                        const float* __restrict__ dinv, float* __restrict__ nrm, int n) {
    int e = blockIdx.x * blockDim.x + threadIdx.x;
    if (e < n) {
        int s = src2[e];
        nrm[e] = (s >= 0) ? dinv[s] * dinv[dst2[e]] : 0.f;
    }
}

// agg[row] = lin[row] * (1/deg[row]) + bias ;  1/deg = dinv^2
__global__ void init_agg_k(const float* __restrict__ lin, const float* __restrict__ dinv,
                           const float* __restrict__ bias, float* __restrict__ agg) {
    int row = blockIdx.x, t = threadIdx.x;         // 256 thr * float4 = 1024
    float iv = dinv[row]; iv *= iv;
    size_t base = (size_t)row * HD + t * 4;
    float4 l = *(const float4*)&lin[base];
    float4 b = *(const float4*)&bias[t * 4];
    float4 o = make_float4(l.x * iv + b.x, l.y * iv + b.y, l.z * iv + b.z, l.w * iv + b.w);
    *(float4*)&agg[base] = o;
}

// warp-per-edge scatter: agg[dst] += lin[src] * norm[e]
__global__ void scatter_k(const float* __restrict__ lin, const int* __restrict__ srcv,
                          const int* __restrict__ dstv, const float* __restrict__ nrm,
                          float* __restrict__ agg, int nE) {
    int warp = (blockIdx.x * blockDim.x + threadIdx.x) >> 5;
    int lane = threadIdx.x & 31;
    if (warp >= nE) return;
    float w = nrm[warp];
    if (w == 0.f) return;
    int s = srcv[warp], d = dstv[warp];
    const float4* xs = (const float4*)(lin + (size_t)s * HD);
    float* base = agg + (size_t)d * HD;
    #pragma unroll
    for (int i = 0; i < 8; i++) {
        float4 v = __ldg(&xs[lane + i * 32]);
        int c = (lane + i * 32) * 4;
        atomicAdd(base + c + 0, v.x * w);
        atomicAdd(base + c + 1, v.y * w);
        atomicAdd(base + c + 2, v.z * w);
        atomicAdd(base + c + 3, v.w * w);
    }
}

// column sums / sumsq (grid.y row chunks), atomics into [HD] accumulators
__global__ void colstats_k(const float* __restrict__ X, int nrows,
                           float* __restrict__ csum, float* __restrict__ csq) {
    int c = blockIdx.x * blockDim.x + threadIdx.x;
    int chunk = (nrows + gridDim.y - 1) / gridDim.y;
    int r0 = blockIdx.y * chunk;
    int r1 = min(r0 + chunk, nrows);
    float s = 0.f, q = 0.f;
    const float* p = X + (size_t)r0 * HD + c;
    for (int r = r0; r < r1; r++, p += HD) { float v = *p; s += v; q += v * v; }
    atomicAdd(&csum[c], s);
    atomicAdd(&csq[c], q);
}

__global__ void bnprep_k(const float* __restrict__ csum, const float* __restrict__ csq,
                         float invn, const float* __restrict__ g, const float* __restrict__ be,
                         float* __restrict__ scale, float* __restrict__ shift) {
    int c = blockIdx.x * blockDim.x + threadIdx.x;
    float m = csum[c] * invn;
    float v = csq[c] * invn - m * m;
    float rs = rsqrtf(v + BN_EPS) * g[c];
    scale[c] = rs;
    shift[c] = be[c] - m * rs;
}

// p normalized by ||p|| (single block, 1024 threads)
__global__ void pnorm_k(const float* __restrict__ p, float* __restrict__ pn) {
    int t = threadIdx.x;
    float v = p[t];
    float s = v * v;
    #pragma unroll
    for (int o = 16; o > 0; o >>= 1) s += __shfl_down_sync(0xffffffff, s, o);
    __shared__ float red[32];
    if ((t & 31) == 0) red[t >> 5] = s;
    __syncthreads();
    if (t < 32) {
        float x = red[t];
        #pragma unroll
        for (int o = 16; o > 0; o >>= 1) x += __shfl_down_sync(0xffffffff, x, o);
        if (t == 0) red[0] = x;
    }
    __syncthreads();
    pn[t] = v * rsqrtf(red[0]);
}

// in-place BN + ReLU, fused score = tanh(h . pn) per row (block per row, 256 thr)
__global__ void bn_relu_score_k(float* __restrict__ X, const float* __restrict__ scale,
                                const float* __restrict__ shift, const float* __restrict__ pn,
                                float* __restrict__ score) {
    int row = blockIdx.x, t = threadIdx.x;
    size_t base = (size_t)row * HD + t * 4;
    float4 v = *(float4*)&X[base];
    float4 sc = *(const float4*)&scale[t * 4];
    float4 sh = *(const float4*)&shift[t * 4];
    v.x = fmaxf(v.x * sc.x + sh.x, 0.f);
    v.y = fmaxf(v.y * sc.y + sh.y, 0.f);
    v.z = fmaxf(v.z * sc.z + sh.z, 0.f);
    v.w = fmaxf(v.w * sc.w + sh.w, 0.f);
    *(float4*)&X[base] = v;
    float4 p = *(const float4*)&pn[t * 4];
    float dot = v.x * p.x + v.y * p.y + v.z * p.z + v.w * p.w;
    #pragma unroll
    for (int o = 16; o > 0; o >>= 1) dot += __shfl_down_sync(0xffffffff, dot, o);
    __shared__ float red[8];
    if ((t & 31) == 0) red[t >> 5] = dot;
    __syncthreads();
    if (t == 0) {
        float s = 0.f;
        #pragma unroll
        for (int i = 0; i < 8; i++) s += red[i];
        score[row] = tanhf(s);
    }
}

// per-graph bitonic full sort (descending, tie -> lower index), emit top-K
template<int NPGT, int KK>
__global__ void topk_k(const float* __restrict__ score, float* __restrict__ val,
                       int* __restrict__ perm, int* __restrict__ newid) {
    __shared__ float s[NPGT];
    __shared__ int   id[NPGT];
    int b = blockIdx.x, t = threadIdx.x;
    s[t] = score[b * NPGT + t];
    id[t] = t;
    for (int size = 2; size <= NPGT; size <<= 1) {
        for (int stride = size >> 1; stride > 0; stride >>= 1) {
            __syncthreads();
            int j = t ^ stride;
            if (j > t) {
                float a = s[t], c = s[j];
                int ia = id[t], ic = id[j];
                bool aFirst = (a > c) || (a == c && ia < ic);   // descending
                bool descHere = ((t & size) == 0);
                if (descHere ? !aFirst : aFirst) {
                    s[t] = c; s[j] = a; id[t] = ic; id[j] = ia;
                }
            }
        }
    }
    __syncthreads();
    if (t < KK) {
        perm[b * KK + t] = b * NPGT + id[t];
        val[b * KK + t] = s[t];
        if (newid) newid[b * NPGT + id[t]] = b * KK + t;
    } else if (newid) {
        newid[b * NPGT + id[t]] = -1;
    }
}

__global__ void gather_k(const float* __restrict__ Hin, const int* __restrict__ perm,
                         const float* __restrict__ val, float* __restrict__ Hout) {
    int row = blockIdx.x, t = threadIdx.x;
    int srow = perm[row];
    float v = val[row];
    float4 x = *(const float4*)&Hin[(size_t)srow * HD + t * 4];
    x.x *= v; x.y *= v; x.z *= v; x.w *= v;
    *(float4*)&Hout[(size_t)row * HD + t * 4] = x;
}

__global__ void remap_k(const int* __restrict__ src, const int* __restrict__ dst,
                        const int* __restrict__ newid, int* __restrict__ src2,
                        int* __restrict__ dst2, int n) {
    int e = blockIdx.x * blockDim.x + threadIdx.x;
    if (e >= n) return;
    int s = newid[src[e]], d = newid[dst[e]];
    if (s < 0 || d < 0) { src2[e] = -1; dst2[e] = 0; }
    else { src2[e] = s; dst2[e] = d; }
}

__global__ void meanpool_k(const float* __restrict__ Hin, float* __restrict__ out, int kpg) {
    int b = blockIdx.x;
    int c = blockIdx.y * 256 + threadIdx.x;
    float sum = 0.f;
    const float* p = Hin + (size_t)b * kpg * HD + c;
    for (int r = 0; r < kpg; r++) sum += p[(size_t)r * HD];
    out[b * HD + c] = sum / (float)kpg;
}

__global__ void fc1_k(const float* __restrict__ x1, const float* __restrict__ x2,
                      const float* __restrict__ Wf, const float* __restrict__ bf,
                      float* __restrict__ z) {
    __shared__ float xs[HD];
    int m = blockIdx.x, c = threadIdx.x;   // 512 threads
    xs[c]       = x1[m * HD + c]       + x2[m * HD + c];
    xs[c + 512] = x1[m * HD + c + 512] + x2[m * HD + c + 512];
    __syncthreads();
    float s = bf[c];
    #pragma unroll 4
    for (int k = 0; k < HD; k++) s += xs[k] * Wf[(size_t)k * FC1D + c];
    z[m * FC1D + c] = fmaxf(s, 0.f);
}

__global__ void fc2_k(const float* __restrict__ z, const float* __restrict__ W,
                      const float* __restrict__ b, float* __restrict__ out) {
    int t = threadIdx.x;
    if (t >= BG * OUTD) return;
    int m = t / OUTD, c = t % OUTD;
    float s = b[c];
    #pragma unroll 4
    for (int k = 0; k < FC1D; k++) s += z[m * FC1D + k] * W[k * OUTD + c];
    out[t] = s;
}

// ---------------- launch ----------------
extern "C" void kernel_launch(void* const* d_in, const int* in_sizes, int n_in,
                              void* d_out, int out_size) {
    (void)in_sizes; (void)n_in; (void)out_size;
    float* FS = nullptr; int* IS = nullptr;
    cudaGetSymbolAddress((void**)&FS, d_fscratch);
    cudaGetSymbolAddress((void**)&IS, d_iscratch);

    const float* x   = (const float*)d_in[0];
    const int*   ei  = (const int*)d_in[1];
    const float* W1  = (const float*)d_in[3];
    const float* b1  = (const float*)d_in[4];
    const float* g1  = (const float*)d_in[5];
    const float* be1 = (const float*)d_in[6];
    const float* p1  = (const float*)d_in[7];
    const float* W2  = (const float*)d_in[8];
    const float* b2  = (const float*)d_in[9];
    const float* g2  = (const float*)d_in[10];
    const float* be2 = (const float*)d_in[11];
    const float* p2  = (const float*)d_in[12];
    const float* Wf  = (const float*)d_in[13];
    const float* bf  = (const float*)d_in[14];
    const float* Wf1 = (const float*)d_in[15];
    const float* bf1 = (const float*)d_in[16];
    float* out = (float*)d_out;

    const int* src = ei;
    const int* dst = ei + E_TOT;

    float* lin1  = FS + F_LIN1;
    float* agg1  = FS + F_AGG1;
    float* hp1   = FS + F_HP1;
    float* lin2  = FS + F_LIN2;
    float* agg2  = FS + F_AGG2;
    float* hp2   = FS + F_HP2;
    float* norm1 = FS + F_NORM1;
    float* norm2 = FS + F_NORM2;
    float* deg1  = FS + F_DEG1;
    float* dinv1 = FS + F_DINV1;
    float* deg2  = FS + F_DEG2;
    float* dinv2 = FS + F_DINV2;
    float* score1= FS + F_SCORE1;
    float* score2= FS + F_SCORE2;
    float* val1  = FS + F_VAL1;
    float* val2  = FS + F_VAL2;
    float* colsum= FS + F_COLSUM;   // colsq is contiguous after
    float* colsq = FS + F_COLSQ;
    float* scale = FS + F_SCALE;
    float* shift = FS + F_SHIFT;
    float* pn    = FS + F_PN;
    float* x1    = FS + F_X1;
    float* x2    = FS + F_X2;
    float* z     = FS + F_Z;

    int* src2  = IS + I_SRC2;
    int* dst2  = IS + I_DST2;
    int* perm1 = IS + I_PERM1;
    int* perm2 = IS + I_PERM2;
    int* newid = IS + I_NEWID;

    // ===== Layer 1: GCNConv(x, W1) =====
    sgemm_k<<<dim3(HD / 128, N1 / 128), 256>>>(x, W1, lin1, N1, HD, F_IN);
    fill_k<<<(N1 + 255) / 256, 256>>>(deg1, N1, 1.0f);
    degcount1_k<<<E_TOT / 256, 256>>>(dst, deg1, E_TOT);
    dinv_k<<<(N1 + 255) / 256, 256>>>(deg1, dinv1, N1);
    norm1_k<<<E_TOT / 256, 256>>>(src, dst, dinv1, norm1, E_TOT);
    init_agg_k<<<N1, 256>>>(lin1, dinv1, b1, agg1);
    scatter_k<<<E_TOT / 8, 256>>>(lin1, src, dst, norm1, agg1, E_TOT);

    // BN1 + ReLU + score1
    fill_k<<<(2 * HD + 255) / 256, 256>>>(colsum, 2 * HD, 0.f);
    colstats_k<<<dim3(HD / 256, 64), 256>>>(agg1, N1, colsum, colsq);
    bnprep_k<<<HD / 256, 256>>>(colsum, colsq, 1.0f / (float)N1, g1, be1, scale, shift);
    pnorm_k<<<1, HD>>>(p1, pn);
    bn_relu_score_k<<<N1, 256>>>(agg1, scale, shift, pn, score1);

    // TopK pool 1 (1024 -> 512 per graph)
    topk_k<NPG, KP1><<<BG, NPG>>>(score1, val1, perm1, newid);
    gather_k<<<N2, 256>>>(agg1, perm1, val1, hp1);
    remap_k<<<E_TOT / 256, 256>>>(src, dst, newid, src2, dst2, E_TOT);
    meanpool_k<<<dim3(BG, HD / 256), 256>>>(hp1, x1, KP1);

    // ===== Layer 2: GCNConv(hp1, W2) =====
    sgemm_k<<<dim3(HD / 128, N2 / 128), 256>>>(hp1, W2, lin2, N2, HD, HD);
    fill_k<<<(N2 + 255) / 256, 256>>>(deg2, N2, 1.0f);
    degcount2_k<<<E_TOT / 256, 256>>>(src2, dst2, deg2, E_TOT);
    dinv_k<<<(N2 + 255) / 256, 256>>>(deg2, dinv2, N2);
    norm2_k<<<E_TOT / 256, 256>>>(src2, dst2, dinv2, norm2, E_TOT);
    init_agg_k<<<N2, 256>>>(lin2, dinv2, b2, agg2);
    scatter_k<<<E_TOT / 8, 256>>>(lin2, src2, dst2, norm2, agg2, E_TOT);

    // BN2 + ReLU + score2
    fill_k<<<(2 * HD + 255) / 256, 256>>>(colsum, 2 * HD, 0.f);
    colstats_k<<<dim3(HD / 256, 32), 256>>>(agg2, N2, colsum, colsq);
    bnprep_k<<<HD / 256, 256>>>(colsum, colsq, 1.0f / (float)N2, g2, be2, scale, shift);
    pnorm_k<<<1, HD>>>(p2, pn);
    bn_relu_score_k<<<N2, 256>>>(agg2, scale, shift, pn, score2);

    // TopK pool 2 (512 -> 256 per graph); edges no longer needed afterwards
    topk_k<KP1, KP2><<<BG, KP1>>>(score2, val2, perm2, nullptr);
    gather_k<<<N3, 256>>>(agg2, perm2, val2, hp2);
    meanpool_k<<<dim3(BG, HD / 256), 256>>>(hp2, x2, KP2);

    // ===== Head =====
    fc1_k<<<BG, FC1D>>>(x1, x2, Wf, bf, z);
    fc2_k<<<1, BG * OUTD>>>(z, Wf1, bf1, out);
}

// round 3
// speedup vs baseline: 1.3928x; 1.3928x over previous
#include <cuda_runtime.h>
#include <cuda_bf16.h>
#include <math.h>
#include <cstdint>

// ---------------- problem constants ----------------
#define BG     32
#define NPG    1024
#define DEGC   8
#define F_IN   512
#define HD     1024
#define OUTD   10
#define E_TOT  (BG*NPG*DEGC)   // 262144
#define N1     (BG*NPG)        // 32768
#define KP1    512
#define N2     (BG*KP1)        // 16384
#define KP2    256
#define N3     (BG*KP2)        // 8192
#define FC1D   512
#define BN_EPS 1e-5f

// ---------------- scratch layout (floats) ----------------
#define F_LIN1   ((size_t)0)
#define F_AGG1   (F_LIN1 + (size_t)N1*HD)
#define F_HP1    (F_AGG1 + (size_t)N1*HD)
#define F_LIN2   (F_HP1  + (size_t)N2*HD)
#define F_AGG2   (F_LIN2 + (size_t)N2*HD)
#define F_HP2    (F_AGG2 + (size_t)N2*HD)
#define F_NORM1  (F_HP2  + (size_t)N3*HD)
#define F_NORM2  (F_NORM1 + E_TOT)
#define F_DEG1   (F_NORM2 + E_TOT)
#define F_DINV1  (F_DEG1 + N1)
#define F_DEG2   (F_DINV1 + N1)
#define F_DINV2  (F_DEG2 + N2)
#define F_SCORE1 (F_DINV2 + N2)
#define F_SCORE2 (F_SCORE1 + N1)
#define F_VAL1   (F_SCORE2 + N2)
#define F_VAL2   (F_VAL1 + N2)
#define F_COLSUM (F_VAL2 + N3)
#define F_COLSQ  (F_COLSUM + HD)
#define F_SCALE  (F_COLSQ + HD)
#define F_SHIFT  (F_SCALE + HD)
#define F_PN     (F_SHIFT + HD)
#define F_X1     (F_PN + HD)
#define F_X2     (F_X1 + BG*HD)
#define F_Z      (F_X2 + BG*HD)
#define F_END    (F_Z + BG*FC1D)

#define I_SRC2   ((size_t)0)
#define I_DST2   (I_SRC2 + E_TOT)
#define I_PERM1  (I_DST2 + E_TOT)
#define I_PERM2  (I_PERM1 + N2)
#define I_NEWID  (I_PERM2 + N3)
#define I_END    (I_NEWID + N1)

__device__ float d_fscratch[F_END];
__device__ int   d_iscratch[I_END];

// bf16 split operands (A' = [hi|hi|lo], B' = [hi|lo|hi], B' stored [N][3K])
__device__ __nv_bfloat16 d_a1s[(size_t)N1 * 3 * F_IN];
__device__ __nv_bfloat16 d_w1s[(size_t)HD * 3 * F_IN];
__device__ __nv_bfloat16 d_a2s[(size_t)N2 * 3 * HD];
__device__ __nv_bfloat16 d_w2s[(size_t)HD * 3 * HD];

// ================= helpers =================
__device__ __forceinline__ uint32_t smem_u32(const void* p) {
    uint32_t a;
    asm("{ .reg .u64 t; cvta.to.shared.u64 t, %1; cvt.u32.u64 %0, t; }" : "=r"(a) : "l"(p));
    return a;
}
#define SWZ128(b) ((b) ^ (((b) >> 3) & 0x70))

__device__ __forceinline__ void cp16(uint32_t dst, const void* src) {
    asm volatile("cp.async.cg.shared.global [%0], [%1], 16;" :: "r"(dst), "l"(src));
}

#define LDSM4(r0, r1, r2, r3, addr) \
    asm volatile("ldmatrix.sync.aligned.m8n8.x4.shared.b16 {%0,%1,%2,%3}, [%4];" \
                 : "=r"(r0), "=r"(r1), "=r"(r2), "=r"(r3) : "r"(addr))

#define MMA16816(d, a, b0, b1) \
    asm volatile("mma.sync.aligned.m16n8k16.row.col.f32.bf16.bf16.f32 " \
                 "{%0,%1,%2,%3}, {%4,%5,%6,%7}, {%8,%9}, {%0,%1,%2,%3};" \
                 : "+f"((d)[0]), "+f"((d)[1]), "+f"((d)[2]), "+f"((d)[3]) \
                 : "r"((a)[0]), "r"((a)[1]), "r"((a)[2]), "r"((a)[3]), \
                   "r"(b0), "r"(b1))

#define GEMM_SMEM_DYN (2 * 32768 + 1024)

// ---- HMMA GEMM: C[M,1024] = A'[M,K3] x B'[1024,K3]^T (bf16 in, fp32 out)
// CTA tile 128x128, K-chunk 64. 8 warps: warp_m = wid&3 (32 rows), warp_n = wid>>2 (64 cols).
__global__ void __launch_bounds__(256, 1) gemm_mma(
    const __nv_bfloat16* __restrict__ A, const __nv_bfloat16* __restrict__ B,
    float* __restrict__ C, int K3)
{
    extern __shared__ char smem[];
    const uint32_t base = (smem_u32(smem) + 1023u) & ~1023u;
    const int tid = threadIdx.x, wid = tid >> 5, lane = tid & 31;
    const int m0 = blockIdx.y * 128;
    const int n0 = blockIdx.x * 128;
    const int wm = (wid & 3) * 32;
    const int wn = (wid >> 2) * 64;

    float acc[2][8][4];
    #pragma unroll
    for (int i = 0; i < 2; i++)
        #pragma unroll
        for (int j = 0; j < 8; j++)
            #pragma unroll
            for (int r = 0; r < 4; r++) acc[i][j][r] = 0.f;

    // per-lane fragment base offsets (bytes within 128Bx128row tile, pre-swizzle)
    const int rA0 = (wm + (lane & 15)) * 128;            // A frag mi=0 row byte
    const int cA  = (lane >> 4) * 16;                    // A frag col byte
    const int rBb = (wn + ((lane >> 4) << 3) + (lane & 7)) * 128;  // B row byte (jj=0)
    const int cB  = ((lane >> 3) & 1) * 16;              // B col byte

    const int nStages = K3 >> 6;

    // preload stage 0
    {
        const __nv_bfloat16* Ab = A + (size_t)m0 * K3;
        const __nv_bfloat16* Bb = B + (size_t)n0 * K3;
        #pragma unroll
        for (int i = 0; i < 4; i++) {
            int c = tid + i * 256, row = c >> 3, c8 = c & 7;
            cp16(base + SWZ128(row * 128 + c8 * 16), Ab + (size_t)row * K3 + c8 * 8);
        }
        #pragma unroll
        for (int i = 0; i < 4; i++) {
            int c = tid + i * 256, row = c >> 3, c8 = c & 7;
            cp16(base + 16384 + SWZ128(row * 128 + c8 * 16), Bb + (size_t)row * K3 + c8 * 8);
        }
        asm volatile("cp.async.commit_group;" ::: "memory");
    }

    for (int ks = 0; ks < nStages; ks++) {
        const int buf = ks & 1;
        if (ks + 1 < nStages) {
            const int nb = (ks + 1) & 1;
            const int k0 = (ks + 1) * 64;
            const __nv_bfloat16* Ab = A + (size_t)m0 * K3 + k0;
            const __nv_bfloat16* Bb = B + (size_t)n0 * K3 + k0;
            uint32_t dA = base + nb * 32768, dB = dA + 16384;
            #pragma unroll
            for (int i = 0; i < 4; i++) {
                int c = tid + i * 256, row = c >> 3, c8 = c & 7;
                cp16(dA + SWZ128(row * 128 + c8 * 16), Ab + (size_t)row * K3 + c8 * 8);
            }
            #pragma unroll
            for (int i = 0; i < 4; i++) {
                int c = tid + i * 256, row = c >> 3, c8 = c & 7;
                cp16(dB + SWZ128(row * 128 + c8 * 16), Bb + (size_t)row * K3 + c8 * 8);
            }
            asm volatile("cp.async.commit_group;" ::: "memory");
            asm volatile("cp.async.wait_group 1;" ::: "memory");
        } else {
            asm volatile("cp.async.wait_group 0;" ::: "memory");
        }
        __syncthreads();

        const uint32_t As = base + buf * 32768;
        const uint32_t Bs = As + 16384;
        #pragma unroll
        for (int kk = 0; kk < 4; kk++) {
            const int kb = kk * 32;
            uint32_t a0[4], a1[4];
            LDSM4(a0[0], a0[1], a0[2], a0[3], As + SWZ128(rA0 + cA + kb));
            LDSM4(a1[0], a1[1], a1[2], a1[3], As + SWZ128(rA0 + 16 * 128 + cA + kb));
            uint32_t bf[4][4];
            #pragma unroll
            for (int jj = 0; jj < 4; jj++)
                LDSM4(bf[jj][0], bf[jj][1], bf[jj][2], bf[jj][3],
                      Bs + SWZ128(rBb + jj * 16 * 128 + cB + kb));
            #pragma unroll
            for (int j = 0; j < 8; j++) {
                const int jj = j >> 1, hh = (j & 1) * 2;
                MMA16816(acc[0][j], a0, bf[jj][hh], bf[jj][hh + 1]);
                MMA16816(acc[1][j], a1, bf[jj][hh], bf[jj][hh + 1]);
            }
        }
        __syncthreads();
    }

    // epilogue: direct global stores (float2 pairs)
    const int rq = lane >> 2, cq = (lane & 3) * 2;
    #pragma unroll
    for (int mi = 0; mi < 2; mi++) {
        int rowb = m0 + wm + mi * 16 + rq;
        #pragma unroll
        for (int j = 0; j < 8; j++) {
            float* p0 = C + (size_t)rowb * HD + n0 + wn + j * 8 + cq;
            *(float2*)p0 = make_float2(acc[mi][j][0], acc[mi][j][1]);
            *(float2*)(p0 + 8 * (size_t)HD) = make_float2(acc[mi][j][2], acc[mi][j][3]);
        }
    }
}

// ---- bf16 split kernels ----
__global__ void asplit_k(const float* __restrict__ X, __nv_bfloat16* __restrict__ O, int kshift) {
    size_t i = (size_t)blockIdx.x * blockDim.x + threadIdx.x;
    const int K = 1 << kshift;
    size_t m = i >> kshift;
    int k = (int)(i & (K - 1));
    float v = X[i];
    __nv_bfloat16 hi = __float2bfloat16(v);
    __nv_bfloat16 lo = __float2bfloat16(v - __bfloat162float(hi));
    __nv_bfloat16* row = O + m * (size_t)(3 * K);
    row[k] = hi; row[K + k] = hi; row[2 * K + k] = lo;
}

__global__ void wsplit_k(const float* __restrict__ W, __nv_bfloat16* __restrict__ O, int K) {
    int i = blockIdx.x * blockDim.x + threadIdx.x;   // over K*1024
    int k = i >> 10, n = i & 1023;
    if (k >= K) return;
    float v = W[i];
    __nv_bfloat16 hi = __float2bfloat16(v);
    __nv_bfloat16 lo = __float2bfloat16(v - __bfloat162float(hi));
    size_t base = (size_t)n * (3 * K);
    O[base + k] = hi; O[base + K + k] = lo; O[base + 2 * K + k] = hi;
}

// ---------------- small kernels ----------------
__global__ void fill_k(float* p, int n, float v) {
    int i = blockIdx.x * blockDim.x + threadIdx.x;
    if (i < n) p[i] = v;
}

__global__ void degcount1_k(const int* __restrict__ dst, float* deg, int n) {
    int e = blockIdx.x * blockDim.x + threadIdx.x;
    if (e < n) atomicAdd(&deg[dst[e]], 1.0f);
}

__global__ void degcount2_k(const int* __restrict__ src2, const int* __restrict__ dst2,
                            float* deg, int n) {
    int e = blockIdx.x * blockDim.x + threadIdx.x;
    if (e < n && src2[e] >= 0) atomicAdd(&deg[dst2[e]], 1.0f);
}

__global__ void dinv_k(const float* __restrict__ deg, float* __restrict__ dinv, int n) {
    int i = blockIdx.x * blockDim.x + threadIdx.x;
    if (i < n) dinv[i] = rsqrtf(deg[i]);
}

__global__ void norm1_k(const int* __restrict__ src, const int* __restrict__ dst,
                        const float* __restrict__ dinv, float* __restrict__ nrm, int n) {
    int e = blockIdx.x * blockDim.x + threadIdx.x;
    if (e < n) nrm[e] = dinv[src[e]] * dinv[dst[e]];
}

__global__ void norm2_k(const int* __restrict__ src2, const int* __restrict__ dst2,
                        const float* __restrict__ dinv, float* __restrict__ nrm, int n) {
    int e = blockIdx.x * blockDim.x + threadIdx.x;
    if (e < n) {
        int s = src2[e];
        nrm[e] = (s >= 0) ? dinv[s] * dinv[dst2[e]] : 0.f;
    }
}

__global__ void init_agg_k(const float* __restrict__ lin, const float* __restrict__ dinv,
                           const float* __restrict__ bias, float* __restrict__ agg) {
    int row = blockIdx.x, t = threadIdx.x;
    float iv = dinv[row]; iv *= iv;
    size_t base = (size_t)row * HD + t * 4;
    float4 l = *(const float4*)&lin[base];
    float4 b = *(const float4*)&bias[t * 4];
    float4 o = make_float4(l.x * iv + b.x, l.y * iv + b.y, l.z * iv + b.z, l.w * iv + b.w);
    *(float4*)&agg[base] = o;
}

__global__ void scatter_k(const float* __restrict__ lin, const int* __restrict__ srcv,
                          const int* __restrict__ dstv, const float* __restrict__ nrm,
                          float* __restrict__ agg, int nE) {
    int warp = (blockIdx.x * blockDim.x + threadIdx.x) >> 5;
    int lane = threadIdx.x & 31;
    if (warp >= nE) return;
    float w = nrm[warp];
    if (w == 0.f) return;
    int s = srcv[warp], d = dstv[warp];
    const float4* xs = (const float4*)(lin + (size_t)s * HD);
    float* base = agg + (size_t)d * HD;
    #pragma unroll
    for (int i = 0; i < 8; i++) {
        float4 v = __ldg(&xs[lane + i * 32]);
        int c = (lane + i * 32) * 4;
        atomicAdd(base + c + 0, v.x * w);
        atomicAdd(base + c + 1, v.y * w);
        atomicAdd(base + c + 2, v.z * w);
        atomicAdd(base + c + 3, v.w * w);
    }
}

__global__ void colstats_k(const float* __restrict__ X, int nrows,
                           float* __restrict__ csum, float* __restrict__ csq) {
    int c = blockIdx.x * blockDim.x + threadIdx.x;
    int chunk = (nrows + gridDim.y - 1) / gridDim.y;
    int r0 = blockIdx.y * chunk;
    int r1 = min(r0 + chunk, nrows);
    float s = 0.f, q = 0.f;
    const float* p = X + (size_t)r0 * HD + c;
    for (int r = r0; r < r1; r++, p += HD) { float v = *p; s += v; q += v * v; }
    atomicAdd(&csum[c], s);
    atomicAdd(&csq[c], q);
}

__global__ void bnprep_k(const float* __restrict__ csum, const float* __restrict__ csq,
                         float invn, const float* __restrict__ g, const float* __restrict__ be,
                         float* __restrict__ scale, float* __restrict__ shift) {
    int c = blockIdx.x * blockDim.x + threadIdx.x;
    float m = csum[c] * invn;
    float v = csq[c] * invn - m * m;
    float rs = rsqrtf(v + BN_EPS) * g[c];
    scale[c] = rs;
    shift[c] = be[c] - m * rs;
}

__global__ void pnorm_k(const float* __restrict__ p, float* __restrict__ pn) {
    int t = threadIdx.x;
    float v = p[t];
    float s = v * v;
    #pragma unroll
    for (int o = 16; o > 0; o >>= 1) s += __shfl_down_sync(0xffffffff, s, o);
    __shared__ float red[32];
    if ((t & 31) == 0) red[t >> 5] = s;
    __syncthreads();
    if (t < 32) {
        float x = red[t];
        #pragma unroll
        for (int o = 16; o > 0; o >>= 1) x += __shfl_down_sync(0xffffffff, x, o);
        if (t == 0) red[0] = x;
    }
    __syncthreads();
    pn[t] = v * rsqrtf(red[0]);
}

__global__ void bn_relu_score_k(float* __restrict__ X, const float* __restrict__ scale,
                                const float* __restrict__ shift, const float* __restrict__ pn,
                                float* __restrict__ score) {
    int row = blockIdx.x, t = threadIdx.x;
    size_t base = (size_t)row * HD + t * 4;
    float4 v = *(float4*)&X[base];
    float4 sc = *(const float4*)&scale[t * 4];
    float4 sh = *(const float4*)&shift[t * 4];
    v.x = fmaxf(v.x * sc.x + sh.x, 0.f);
    v.y = fmaxf(v.y * sc.y + sh.y, 0.f);
    v.z = fmaxf(v.z * sc.z + sh.z, 0.f);
    v.w = fmaxf(v.w * sc.w + sh.w, 0.f);
    *(float4*)&X[base] = v;
    float4 p = *(const float4*)&pn[t * 4];
    float dot = v.x * p.x + v.y * p.y + v.z * p.z + v.w * p.w;
    #pragma unroll
    for (int o = 16; o > 0; o >>= 1) dot += __shfl_down_sync(0xffffffff, dot, o);
    __shared__ float red[8];
    if ((t & 31) == 0) red[t >> 5] = dot;
    __syncthreads();
    if (t == 0) {
        float s = 0.f;
        #pragma unroll
        for (int i = 0; i < 8; i++) s += red[i];
        score[row] = tanhf(s);
    }
}

template<int NPGT, int KK>
__global__ void topk_k(const float* __restrict__ score, float* __restrict__ val,
                       int* __restrict__ perm, int* __restrict__ newid) {
    __shared__ float s[NPGT];
    __shared__ int   id[NPGT];
    int b = blockIdx.x, t = threadIdx.x;
    s[t] = score[b * NPGT + t];
    id[t] = t;
    for (int size = 2; size <= NPGT; size <<= 1) {
        for (int stride = size >> 1; stride > 0; stride >>= 1) {
            __syncthreads();
            int j = t ^ stride;
            if (j > t) {
                float a = s[t], c = s[j];
                int ia = id[t], ic = id[j];
                bool aFirst = (a > c) || (a == c && ia < ic);
                bool descHere = ((t & size) == 0);
                if (descHere ? !aFirst : aFirst) {
                    s[t] = c; s[j] = a; id[t] = ic; id[j] = ia;
                }
            }
        }
    }
    __syncthreads();
    if (t < KK) {
        perm[b * KK + t] = b * NPGT + id[t];
        val[b * KK + t] = s[t];
        if (newid) newid[b * NPGT + id[t]] = b * KK + t;
    } else if (newid) {
        newid[b * NPGT + id[t]] = -1;
    }
}

__global__ void gather_k(const float* __restrict__ Hin, const int* __restrict__ perm,
                         const float* __restrict__ val, float* __restrict__ Hout) {
    int row = blockIdx.x, t = threadIdx.x;
    int srow = perm[row];
    float v = val[row];
    float4 x = *(const float4*)&Hin[(size_t)srow * HD + t * 4];
    x.x *= v; x.y *= v; x.z *= v; x.w *= v;
    *(float4*)&Hout[(size_t)row * HD + t * 4] = x;
}

__global__ void remap_k(const int* __restrict__ src, const int* __restrict__ dst,
                        const int* __restrict__ newid, int* __restrict__ src2,
                        int* __restrict__ dst2, int n) {
    int e = blockIdx.x * blockDim.x + threadIdx.x;
    if (e >= n) return;
    int s = newid[src[e]], d = newid[dst[e]];
    if (s < 0 || d < 0) { src2[e] = -1; dst2[e] = 0; }
    else { src2[e] = s; dst2[e] = d; }
}

__global__ void meanpool_k(const float* __restrict__ Hin, float* __restrict__ out, int kpg) {
    int b = blockIdx.x;
    int c = blockIdx.y * 256 + threadIdx.x;
    float sum = 0.f;
    const float* p = Hin + (size_t)b * kpg * HD + c;
    for (int r = 0; r < kpg; r++) sum += p[(size_t)r * HD];
    out[b * HD + c] = sum / (float)kpg;
}

__global__ void fc1_k(const float* __restrict__ x1, const float* __restrict__ x2,
                      const float* __restrict__ Wf, const float* __restrict__ bf,
                      float* __restrict__ z) {
    __shared__ float xs[HD];
    int m = blockIdx.x, c = threadIdx.x;
    xs[c]       = x1[m * HD + c]       + x2[m * HD + c];
    xs[c + 512] = x1[m * HD + c + 512] + x2[m * HD + c + 512];
    __syncthreads();
    float s = bf[c];
    #pragma unroll 4
    for (int k = 0; k < HD; k++) s += xs[k] * Wf[(size_t)k * FC1D + c];
    z[m * FC1D + c] = fmaxf(s, 0.f);
}

__global__ void fc2_k(const float* __restrict__ z, const float* __restrict__ W,
                      const float* __restrict__ b, float* __restrict__ out) {
    int t = threadIdx.x;
    if (t >= BG * OUTD) return;
    int m = t / OUTD, c = t % OUTD;
    float s = b[c];
    #pragma unroll 4
    for (int k = 0; k < FC1D; k++) s += z[m * FC1D + k] * W[k * OUTD + c];
    out[t] = s;
}

// ---------------- launch ----------------
extern "C" void kernel_launch(void* const* d_in, const int* in_sizes, int n_in,
                              void* d_out, int out_size) {
    (void)in_sizes; (void)n_in; (void)out_size;
    float* FS = nullptr; int* IS = nullptr;
    __nv_bfloat16 *a1s = nullptr, *w1s = nullptr, *a2s = nullptr, *w2s = nullptr;
    cudaGetSymbolAddress((void**)&FS, d_fscratch);
    cudaGetSymbolAddress((void**)&IS, d_iscratch);
    cudaGetSymbolAddress((void**)&a1s, d_a1s);
    cudaGetSymbolAddress((void**)&w1s, d_w1s);
    cudaGetSymbolAddress((void**)&a2s, d_a2s);
    cudaGetSymbolAddress((void**)&w2s, d_w2s);
    cudaFuncSetAttribute(gemm_mma, cudaFuncAttributeMaxDynamicSharedMemorySize, GEMM_SMEM_DYN);

    const float* x   = (const float*)d_in[0];
    const int*   ei  = (const int*)d_in[1];
    const float* W1  = (const float*)d_in[3];
    const float* b1  = (const float*)d_in[4];
    const float* g1  = (const float*)d_in[5];
    const float* be1 = (const float*)d_in[6];
    const float* p1  = (const float*)d_in[7];
    const float* W2  = (const float*)d_in[8];
    const float* b2  = (const float*)d_in[9];
    const float* g2  = (const float*)d_in[10];
    const float* be2 = (const float*)d_in[11];
    const float* p2  = (const float*)d_in[12];
    const float* Wf  = (const float*)d_in[13];
    const float* bf  = (const float*)d_in[14];
    const float* Wf1 = (const float*)d_in[15];
    const float* bf1 = (const float*)d_in[16];
    float* out = (float*)d_out;

    const int* src = ei;
    const int* dst = ei + E_TOT;

    float* lin1  = FS + F_LIN1;
    float* agg1  = FS + F_AGG1;
    float* hp1   = FS + F_HP1;
    float* lin2  = FS + F_LIN2;
    float* agg2  = FS + F_AGG2;
    float* hp2   = FS + F_HP2;
    float* norm1 = FS + F_NORM1;
    float* norm2 = FS + F_NORM2;
    float* deg1  = FS + F_DEG1;
    float* dinv1 = FS + F_DINV1;
    float* deg2  = FS + F_DEG2;
    float* dinv2 = FS + F_DINV2;
    float* score1= FS + F_SCORE1;
    float* score2= FS + F_SCORE2;
    float* val1  = FS + F_VAL1;
    float* val2  = FS + F_VAL2;
    float* colsum= FS + F_COLSUM;
    float* colsq = FS + F_COLSQ;
    float* scale = FS + F_SCALE;
    float* shift = FS + F_SHIFT;
    float* pn    = FS + F_PN;
    float* x1    = FS + F_X1;
    float* x2    = FS + F_X2;
    float* z     = FS + F_Z;

    int* src2  = IS + I_SRC2;
    int* dst2  = IS + I_DST2;
    int* perm1 = IS + I_PERM1;
    int* perm2 = IS + I_PERM2;
    int* newid = IS + I_NEWID;

    // ===== Layer 1: GCNConv(x, W1) via HMMA split-bf16 =====
    asplit_k<<<(int)(((size_t)N1 * F_IN) / 256), 256>>>(x, a1s, 9);
    wsplit_k<<<(F_IN * HD) / 256, 256>>>(W1, w1s, F_IN);
    gemm_mma<<<dim3(HD / 128, N1 / 128), 256, GEMM_SMEM_DYN>>>(a1s, w1s, lin1, 3 * F_IN);

    fill_k<<<(N1 + 255) / 256, 256>>>(deg1, N1, 1.0f);
    degcount1_k<<<E_TOT / 256, 256>>>(dst, deg1, E_TOT);
    dinv_k<<<(N1 + 255) / 256, 256>>>(deg1, dinv1, N1);
    norm1_k<<<E_TOT / 256, 256>>>(src, dst, dinv1, norm1, E_TOT);
    init_agg_k<<<N1, 256>>>(lin1, dinv1, b1, agg1);
    scatter_k<<<E_TOT / 8, 256>>>(lin1, src, dst, norm1, agg1, E_TOT);

    fill_k<<<(2 * HD + 255) / 256, 256>>>(colsum, 2 * HD, 0.f);
    colstats_k<<<dim3(HD / 256, 64), 256>>>(agg1, N1, colsum, colsq);
    bnprep_k<<<HD / 256, 256>>>(colsum, colsq, 1.0f / (float)N1, g1, be1, scale, shift);
    pnorm_k<<<1, HD>>>(p1, pn);
    bn_relu_score_k<<<N1, 256>>>(agg1, scale, shift, pn, score1);

    topk_k<NPG, KP1><<<BG, NPG>>>(score1, val1, perm1, newid);
    gather_k<<<N2, 256>>>(agg1, perm1, val1, hp1);
    remap_k<<<E_TOT / 256, 256>>>(src, dst, newid, src2, dst2, E_TOT);
    meanpool_k<<<dim3(BG, HD / 256), 256>>>(hp1, x1, KP1);

    // ===== Layer 2: GCNConv(hp1, W2) via HMMA split-bf16 =====
    asplit_k<<<(int)(((size_t)N2 * HD) / 256), 256>>>(hp1, a2s, 10);
    wsplit_k<<<(HD * HD) / 256, 256>>>(W2, w2s, HD);
    gemm_mma<<<dim3(HD / 128, N2 / 128), 256, GEMM_SMEM_DYN>>>(a2s, w2s, lin2, 3 * HD);

    fill_k<<<(N2 + 255) / 256, 256>>>(deg2, N2, 1.0f);
    degcount2_k<<<E_TOT / 256, 256>>>(src2, dst2, deg2, E_TOT);
    dinv_k<<<(N2 + 255) / 256, 256>>>(deg2, dinv2, N2);
    norm2_k<<<E_TOT / 256, 256>>>(src2, dst2, dinv2, norm2, E_TOT);
    init_agg_k<<<N2, 256>>>(lin2, dinv2, b2, agg2);
    scatter_k<<<E_TOT / 8, 256>>>(lin2, src2, dst2, norm2, agg2, E_TOT);

    fill_k<<<(2 * HD + 255) / 256, 256>>>(colsum, 2 * HD, 0.f);
    colstats_k<<<dim3(HD / 256, 32), 256>>>(agg2, N2, colsum, colsq);
    bnprep_k<<<HD / 256, 256>>>(colsum, colsq, 1.0f / (float)N2, g2, be2, scale, shift);
    pnorm_k<<<1, HD>>>(p2, pn);
    bn_relu_score_k<<<N2, 256>>>(agg2, scale, shift, pn, score2);

    topk_k<KP1, KP2><<<BG, KP1>>>(score2, val2, perm2, nullptr);
    gather_k<<<N3, 256>>>(agg2, perm2, val2, hp2);
    meanpool_k<<<dim3(BG, HD / 256), 256>>>(hp2, x2, KP2);

    // ===== Head =====
    fc1_k<<<BG, FC1D>>>(x1, x2, Wf, bf, z);
    fc2_k<<<1, BG * OUTD>>>(z, Wf1, bf1, out);
}

// round 4
// speedup vs baseline: 2.2192x; 1.5934x over previous
#include <cuda_runtime.h>
#include <cuda_bf16.h>
#include <math.h>
#include <cstdint>

// ---------------- problem constants ----------------
#define BG     32
#define NPG    1024
#define DEGC   8
#define F_IN   512
#define HD     1024
#define OUTD   10
#define E_TOT  (BG*NPG*DEGC)   // 262144
#define EPG    (NPG*DEGC)      // 8192 edges per graph
#define N1     (BG*NPG)        // 32768
#define KP1    512
#define N2     (BG*KP1)        // 16384
#define KP2    256
#define N3     (BG*KP2)        // 8192
#define FC1D   512
#define BN_EPS 1e-5f

// ---------------- scratch layout (floats) ----------------
#define F_LIN1   ((size_t)0)
#define F_AGG1   (F_LIN1 + (size_t)N1*HD)
#define F_HP1    (F_AGG1 + (size_t)N1*HD)
#define F_LIN2   (F_HP1  + (size_t)N2*HD)
#define F_AGG2   (F_LIN2 + (size_t)N2*HD)
#define F_HP2    (F_AGG2 + (size_t)N2*HD)
#define F_DINV1  (F_HP2  + (size_t)N3*HD)
#define F_DINV2  (F_DINV1 + N1)
#define F_SCORE1 (F_DINV2 + N2)
#define F_SCORE2 (F_SCORE1 + N1)
#define F_VAL1   (F_SCORE2 + N2)
#define F_VAL2   (F_VAL1 + N2)
#define F_COLSUM (F_VAL2 + N3)
#define F_COLSQ  (F_COLSUM + HD)
#define F_SCALE  (F_COLSQ + HD)
#define F_SHIFT  (F_SCALE + HD)
#define F_PN     (F_SHIFT + HD)
#define F_X1     (F_PN + HD)
#define F_X2     (F_X1 + BG*HD)
#define F_Z      (F_X2 + BG*HD)
#define F_END    (F_Z + BG*FC1D)

#define I_SRC2   ((size_t)0)
#define I_DST2   (I_SRC2 + E_TOT)
#define I_CSR    (I_DST2 + E_TOT)        // shared by both layers
#define I_CNT1   (I_CSR + E_TOT)
#define I_OFF1   (I_CNT1 + N1)
#define I_CUR1   (I_OFF1 + N1)
#define I_CNT2   (I_CUR1 + N1)
#define I_OFF2   (I_CNT2 + N2)
#define I_CUR2   (I_OFF2 + N2)
#define I_PERM1  (I_CUR2 + N2)
#define I_PERM2  (I_PERM1 + N2)
#define I_NEWID  (I_PERM2 + N3)
#define I_END    (I_NEWID + N1)

__device__ float d_fscratch[F_END];
__device__ int   d_iscratch[I_END];

// bf16 split operands (A' = [hi|hi|lo], B' = [hi|lo|hi], B' stored [N][3K])
__device__ __nv_bfloat16 d_a1s[(size_t)N1 * 3 * F_IN];
__device__ __nv_bfloat16 d_w1s[(size_t)HD * 3 * F_IN];
__device__ __nv_bfloat16 d_a2s[(size_t)N2 * 3 * HD];
__device__ __nv_bfloat16 d_w2s[(size_t)HD * 3 * HD];

// ================= helpers =================
__device__ __forceinline__ uint32_t smem_u32(const void* p) {
    uint32_t a;
    asm("{ .reg .u64 t; cvta.to.shared.u64 t, %1; cvt.u32.u64 %0, t; }" : "=r"(a) : "l"(p));
    return a;
}
#define SWZ128(b) ((b) ^ (((b) >> 3) & 0x70))

__device__ __forceinline__ void cp16(uint32_t dst, const void* src) {
    asm volatile("cp.async.cg.shared.global [%0], [%1], 16;" :: "r"(dst), "l"(src));
}

#define LDSM4(r0, r1, r2, r3, addr) \
    asm volatile("ldmatrix.sync.aligned.m8n8.x4.shared.b16 {%0,%1,%2,%3}, [%4];" \
                 : "=r"(r0), "=r"(r1), "=r"(r2), "=r"(r3) : "r"(addr))

#define MMA16816(d, a, b0, b1) \
    asm volatile("mma.sync.aligned.m16n8k16.row.col.f32.bf16.bf16.f32 " \
                 "{%0,%1,%2,%3}, {%4,%5,%6,%7}, {%8,%9}, {%0,%1,%2,%3};" \
                 : "+f"((d)[0]), "+f"((d)[1]), "+f"((d)[2]), "+f"((d)[3]) \
                 : "r"((a)[0]), "r"((a)[1]), "r"((a)[2]), "r"((a)[3]), \
                   "r"(b0), "r"(b1))

#define GEMM_SMEM_DYN (4 * 32768 + 1024)

// ---- HMMA GEMM: C[M,1024] = A'[M,K3] x B'[1024,K3]^T (bf16 in, fp32 out)
// CTA tile 128x128, K-chunk 64, 4-stage cp.async ring. 8 warps: 32x64 each.
__global__ void __launch_bounds__(256, 1) gemm_mma(
    const __nv_bfloat16* __restrict__ A, const __nv_bfloat16* __restrict__ B,
    float* __restrict__ C, int K3)
{
    extern __shared__ char smem[];
    const uint32_t base = (smem_u32(smem) + 1023u) & ~1023u;
    const int tid = threadIdx.x, wid = tid >> 5, lane = tid & 31;
    const int m0 = blockIdx.y * 128;
    const int n0 = blockIdx.x * 128;
    const int wm = (wid & 3) * 32;
    const int wn = (wid >> 2) * 64;

    float acc[2][8][4];
    #pragma unroll
    for (int i = 0; i < 2; i++)
        #pragma unroll
        for (int j = 0; j < 8; j++)
            #pragma unroll
            for (int r = 0; r < 4; r++) acc[i][j][r] = 0.f;

    const int rA0 = (wm + (lane & 15)) * 128;
    const int cA  = (lane >> 4) * 16;
    const int rBb = (wn + ((lane >> 4) << 3) + (lane & 7)) * 128;
    const int cB  = ((lane >> 3) & 1) * 16;

    const int nStages = K3 >> 6;
    const __nv_bfloat16* Abase = A + (size_t)m0 * K3;
    const __nv_bfloat16* Bbase = B + (size_t)n0 * K3;
    const int lrow = tid >> 3, lc8 = tid & 7;   // per-thread load coords

    // prologue: stages 0,1,2 (one commit group each)
    #pragma unroll
    for (int s = 0; s < 3; s++) {
        uint32_t dA = base + s * 32768, dB = dA + 16384;
        const __nv_bfloat16* Ab = Abase + s * 64;
        const __nv_bfloat16* Bb = Bbase + s * 64;
        #pragma unroll
        for (int i = 0; i < 4; i++) {
            int row = lrow + i * 32;
            cp16(dA + SWZ128(row * 128 + lc8 * 16), Ab + (size_t)row * K3 + lc8 * 8);
            cp16(dB + SWZ128(row * 128 + lc8 * 16), Bb + (size_t)row * K3 + lc8 * 8);
        }
        asm volatile("cp.async.commit_group;" ::: "memory");
    }

    for (int ks = 0; ks < nStages; ks++) {
        asm volatile("cp.async.wait_group 2;" ::: "memory");   // stage ks ready
        __syncthreads();                                       // all warps done ks-1

        if (ks + 3 < nStages) {                                // prefetch ks+3
            uint32_t dA = base + ((ks + 3) & 3) * 32768, dB = dA + 16384;
            const __nv_bfloat16* Ab = Abase + (ks + 3) * 64;
            const __nv_bfloat16* Bb = Bbase + (ks + 3) * 64;
            #pragma unroll
            for (int i = 0; i < 4; i++) {
                int row = lrow + i * 32;
                cp16(dA + SWZ128(row * 128 + lc8 * 16), Ab + (size_t)row * K3 + lc8 * 8);
                cp16(dB + SWZ128(row * 128 + lc8 * 16), Bb + (size_t)row * K3 + lc8 * 8);
            }
        }
        asm volatile("cp.async.commit_group;" ::: "memory");   // (possibly empty)

        const uint32_t As = base + (ks & 3) * 32768;
        const uint32_t Bs = As + 16384;
        #pragma unroll
        for (int kk = 0; kk < 4; kk++) {
            const int kb = kk * 32;
            uint32_t a0[4], a1[4];
            LDSM4(a0[0], a0[1], a0[2], a0[3], As + SWZ128(rA0 + cA + kb));
            LDSM4(a1[0], a1[1], a1[2], a1[3], As + SWZ128(rA0 + 16 * 128 + cA + kb));
            uint32_t bf[4][4];
            #pragma unroll
            for (int jj = 0; jj < 4; jj++)
                LDSM4(bf[jj][0], bf[jj][1], bf[jj][2], bf[jj][3],
                      Bs + SWZ128(rBb + jj * 16 * 128 + cB + kb));
            #pragma unroll
            for (int j = 0; j < 8; j++) {
                const int jj = j >> 1, hh = (j & 1) * 2;
                MMA16816(acc[0][j], a0, bf[jj][hh], bf[jj][hh + 1]);
                MMA16816(acc[1][j], a1, bf[jj][hh], bf[jj][hh + 1]);
            }
        }
    }

    const int rq = lane >> 2, cq = (lane & 3) * 2;
    #pragma unroll
    for (int mi = 0; mi < 2; mi++) {
        int rowb = m0 + wm + mi * 16 + rq;
        #pragma unroll
        for (int j = 0; j < 8; j++) {
            float* p0 = C + (size_t)rowb * HD + n0 + wn + j * 8 + cq;
            *(float2*)p0 = make_float2(acc[mi][j][0], acc[mi][j][1]);
            *(float2*)(p0 + 8 * (size_t)HD) = make_float2(acc[mi][j][2], acc[mi][j][3]);
        }
    }
}

// ---- bf16 split kernels ----
__global__ void asplit_k(const float* __restrict__ X, __nv_bfloat16* __restrict__ O, int kshift) {
    size_t i = (size_t)blockIdx.x * blockDim.x + threadIdx.x;
    const int K = 1 << kshift;
    size_t m = i >> kshift;
    int k = (int)(i & (K - 1));
    float v = X[i];
    __nv_bfloat16 hi = __float2bfloat16(v);
    __nv_bfloat16 lo = __float2bfloat16(v - __bfloat162float(hi));
    __nv_bfloat16* row = O + m * (size_t)(3 * K);
    row[k] = hi; row[K + k] = hi; row[2 * K + k] = lo;
}

__global__ void wsplit_k(const float* __restrict__ W, __nv_bfloat16* __restrict__ O, int K) {
    int i = blockIdx.x * blockDim.x + threadIdx.x;   // over K*1024
    int k = i >> 10, n = i & 1023;
    if (k >= K) return;
    float v = W[i];
    __nv_bfloat16 hi = __float2bfloat16(v);
    __nv_bfloat16 lo = __float2bfloat16(v - __bfloat162float(hi));
    size_t base = (size_t)n * (3 * K);
    O[base + k] = hi; O[base + K + k] = lo; O[base + 2 * K + k] = hi;
}

// ---------------- CSR build ----------------
__global__ void zero_int_k(int* p, int n) {
    int i = blockIdx.x * blockDim.x + threadIdx.x;
    if (i < n) p[i] = 0;
}

// count in-edges per node (layer1: all valid; layer2: src>=0)
__global__ void count_k(const int* __restrict__ srcv, const int* __restrict__ dstv,
                        int* __restrict__ cnt, int n, int checkValid) {
    int e = blockIdx.x * blockDim.x + threadIdx.x;
    if (e >= n) return;
    if (checkValid && srcv[e] < 0) return;
    atomicAdd(&cnt[dstv[e]], 1);
}

// per-graph exclusive scan of counts -> offsets (base b*EPG); also fills cursor
template<int NPGT>
__global__ void scan_off_k(const int* __restrict__ cnt, int* __restrict__ off,
                           int* __restrict__ cursor) {
    __shared__ int sh[NPGT];
    int b = blockIdx.x, t = threadIdx.x;
    int v = cnt[b * NPGT + t];
    sh[t] = v;
    __syncthreads();
    #pragma unroll
    for (int d = 1; d < NPGT; d <<= 1) {
        int add = (t >= d) ? sh[t - d] : 0;
        __syncthreads();
        sh[t] += add;
        __syncthreads();
    }
    int o = b * EPG + sh[t] - v;   // exclusive
    off[b * NPGT + t] = o;
    cursor[b * NPGT + t] = o;
}

__global__ void fill_csr_k(const int* __restrict__ srcv, const int* __restrict__ dstv,
                           int* __restrict__ cursor, int* __restrict__ csr, int n, int checkValid) {
    int e = blockIdx.x * blockDim.x + threadIdx.x;
    if (e >= n) return;
    int s = srcv[e];
    if (checkValid && s < 0) return;
    int pos = atomicAdd(&cursor[dstv[e]], 1);
    csr[pos] = s;
}

__global__ void dinv_from_cnt_k(const int* __restrict__ cnt, float* __restrict__ dinv, int n) {
    int i = blockIdx.x * blockDim.x + threadIdx.x;
    if (i < n) dinv[i] = rsqrtf(1.0f + (float)cnt[i]);
}

// ---- CSR gather aggregation: agg[n] = lin[n]/deg[n] + bias + sum_e lin[src]*norm ----
__global__ void __launch_bounds__(256) agg_gather_k(
    const float* __restrict__ lin, const int* __restrict__ csr,
    const int* __restrict__ off, const int* __restrict__ cnt,
    const float* __restrict__ dinv, const float* __restrict__ bias,
    float* __restrict__ agg)
{
    const int n = blockIdx.x, t = threadIdx.x;
    const float iv = dinv[n];
    const int o = off[n], c = cnt[n];
    float4 b = ((const float4*)bias)[t];
    float4 l = ((const float4*)(lin + (size_t)n * HD))[t];
    const float iv2 = iv * iv;
    float4 acc = make_float4(fmaf(l.x, iv2, b.x), fmaf(l.y, iv2, b.y),
                             fmaf(l.z, iv2, b.z), fmaf(l.w, iv2, b.w));
    int j = 0;
    for (; j + 1 < c; j += 2) {
        int s0 = __ldg(&csr[o + j]), s1 = __ldg(&csr[o + j + 1]);
        float w0 = __ldg(&dinv[s0]) * iv, w1 = __ldg(&dinv[s1]) * iv;
        float4 v0 = ((const float4*)(lin + (size_t)s0 * HD))[t];
        float4 v1 = ((const float4*)(lin + (size_t)s1 * HD))[t];
        acc.x += v0.x * w0 + v1.x * w1;
        acc.y += v0.y * w0 + v1.y * w1;
        acc.z += v0.z * w0 + v1.z * w1;
        acc.w += v0.w * w0 + v1.w * w1;
    }
    if (j < c) {
        int s0 = __ldg(&csr[o + j]);
        float w0 = __ldg(&dinv[s0]) * iv;
        float4 v0 = ((const float4*)(lin + (size_t)s0 * HD))[t];
        acc.x += v0.x * w0; acc.y += v0.y * w0;
        acc.z += v0.z * w0; acc.w += v0.w * w0;
    }
    ((float4*)(agg + (size_t)n * HD))[t] = acc;
}

// ---------------- BN / score / pooling ----------------
__global__ void fill_k(float* p, int n, float v) {
    int i = blockIdx.x * blockDim.x + threadIdx.x;
    if (i < n) p[i] = v;
}

__global__ void colstats_k(const float* __restrict__ X, int nrows,
                           float* __restrict__ csum, float* __restrict__ csq) {
    int c = blockIdx.x * blockDim.x + threadIdx.x;
    int chunk = (nrows + gridDim.y - 1) / gridDim.y;
    int r0 = blockIdx.y * chunk;
    int r1 = min(r0 + chunk, nrows);
    float s = 0.f, q = 0.f;
    const float* p = X + (size_t)r0 * HD + c;
    for (int r = r0; r < r1; r++, p += HD) { float v = *p; s += v; q += v * v; }
    atomicAdd(&csum[c], s);
    atomicAdd(&csq[c], q);
}

__global__ void bnprep_k(const float* __restrict__ csum, const float* __restrict__ csq,
                         float invn, const float* __restrict__ g, const float* __restrict__ be,
                         float* __restrict__ scale, float* __restrict__ shift) {
    int c = blockIdx.x * blockDim.x + threadIdx.x;
    float m = csum[c] * invn;
    float v = csq[c] * invn - m * m;
    float rs = rsqrtf(v + BN_EPS) * g[c];
    scale[c] = rs;
    shift[c] = be[c] - m * rs;
}

__global__ void pnorm_k(const float* __restrict__ p, float* __restrict__ pn) {
    int t = threadIdx.x;
    float v = p[t];
    float s = v * v;
    #pragma unroll
    for (int o = 16; o > 0; o >>= 1) s += __shfl_down_sync(0xffffffff, s, o);
    __shared__ float red[32];
    if ((t & 31) == 0) red[t >> 5] = s;
    __syncthreads();
    if (t < 32) {
        float x = red[t];
        #pragma unroll
        for (int o = 16; o > 0; o >>= 1) x += __shfl_down_sync(0xffffffff, x, o);
        if (t == 0) red[0] = x;
    }
    __syncthreads();
    pn[t] = v * rsqrtf(red[0]);
}

__global__ void bn_relu_score_k(float* __restrict__ X, const float* __restrict__ scale,
                                const float* __restrict__ shift, const float* __restrict__ pn,
                                float* __restrict__ score) {
    int row = blockIdx.x, t = threadIdx.x;
    size_t base = (size_t)row * HD + t * 4;
    float4 v = *(float4*)&X[base];
    float4 sc = *(const float4*)&scale[t * 4];
    float4 sh = *(const float4*)&shift[t * 4];
    v.x = fmaxf(v.x * sc.x + sh.x, 0.f);
    v.y = fmaxf(v.y * sc.y + sh.y, 0.f);
    v.z = fmaxf(v.z * sc.z + sh.z, 0.f);
    v.w = fmaxf(v.w * sc.w + sh.w, 0.f);
    *(float4*)&X[base] = v;
    float4 p = *(const float4*)&pn[t * 4];
    float dot = v.x * p.x + v.y * p.y + v.z * p.z + v.w * p.w;
    #pragma unroll
    for (int o = 16; o > 0; o >>= 1) dot += __shfl_down_sync(0xffffffff, dot, o);
    __shared__ float red[8];
    if ((t & 31) == 0) red[t >> 5] = dot;
    __syncthreads();
    if (t == 0) {
        float s = 0.f;
        #pragma unroll
        for (int i = 0; i < 8; i++) s += red[i];
        score[row] = tanhf(s);
    }
}

template<int NPGT, int KK>
__global__ void topk_k(const float* __restrict__ score, float* __restrict__ val,
                       int* __restrict__ perm, int* __restrict__ newid) {
    __shared__ float s[NPGT];
    __shared__ int   id[NPGT];
    int b = blockIdx.x, t = threadIdx.x;
    s[t] = score[b * NPGT + t];
    id[t] = t;
    for (int size = 2; size <= NPGT; size <<= 1) {
        for (int stride = size >> 1; stride > 0; stride >>= 1) {
            __syncthreads();
            int j = t ^ stride;
            if (j > t) {
                float a = s[t], c = s[j];
                int ia = id[t], ic = id[j];
                bool aFirst = (a > c) || (a == c && ia < ic);
                bool descHere = ((t & size) == 0);
                if (descHere ? !aFirst : aFirst) {
                    s[t] = c; s[j] = a; id[t] = ic; id[j] = ia;
                }
            }
        }
    }
    __syncthreads();
    if (t < KK) {
        perm[b * KK + t] = b * NPGT + id[t];
        val[b * KK + t] = s[t];
        if (newid) newid[b * NPGT + id[t]] = b * KK + t;
    } else if (newid) {
        newid[b * NPGT + id[t]] = -1;
    }
}

// pooled gather; optionally also emits bf16 3-split row for next GEMM
__global__ void gather_split_k(const float* __restrict__ Hin, const int* __restrict__ perm,
                               const float* __restrict__ val, float* __restrict__ Hout,
                               __nv_bfloat16* __restrict__ As) {
    int row = blockIdx.x, t = threadIdx.x;
    int srow = perm[row];
    float v = val[row];
    float4 x = *(const float4*)&Hin[(size_t)srow * HD + t * 4];
    x.x *= v; x.y *= v; x.z *= v; x.w *= v;
    *(float4*)&Hout[(size_t)row * HD + t * 4] = x;
    if (As) {
        __nv_bfloat16* rp = As + (size_t)row * (3 * HD);
        int k = t * 4;
        float vs[4] = {x.x, x.y, x.z, x.w};
        #pragma unroll
        for (int i = 0; i < 4; i++) {
            __nv_bfloat16 hi = __float2bfloat16(vs[i]);
            __nv_bfloat16 lo = __float2bfloat16(vs[i] - __bfloat162float(hi));
            rp[k + i] = hi; rp[HD + k + i] = hi; rp[2 * HD + k + i] = lo;
        }
    }
}

__global__ void remap_k(const int* __restrict__ src, const int* __restrict__ dst,
                        const int* __restrict__ newid, int* __restrict__ src2,
                        int* __restrict__ dst2, int n) {
    int e = blockIdx.x * blockDim.x + threadIdx.x;
    if (e >= n) return;
    int s = newid[src[e]], d = newid[dst[e]];
    if (s < 0 || d < 0) { src2[e] = -1; dst2[e] = 0; }
    else { src2[e] = s; dst2[e] = d; }
}

__global__ void meanpool_k(const float* __restrict__ Hin, float* __restrict__ out, int kpg) {
    int b = blockIdx.x;
    int c = blockIdx.y * 256 + threadIdx.x;
    float sum = 0.f;
    const float* p = Hin + (size_t)b * kpg * HD + c;
    for (int r = 0; r < kpg; r++) sum += p[(size_t)r * HD];
    out[b * HD + c] = sum / (float)kpg;
}

__global__ void fc1_k(const float* __restrict__ x1, const float* __restrict__ x2,
                      const float* __restrict__ Wf, const float* __restrict__ bf,
                      float* __restrict__ z) {
    __shared__ float xs[HD];
    int m = blockIdx.x, c = threadIdx.x;
    xs[c]       = x1[m * HD + c]       + x2[m * HD + c];
    xs[c + 512] = x1[m * HD + c + 512] + x2[m * HD + c + 512];
    __syncthreads();
    float s = bf[c];
    #pragma unroll 4
    for (int k = 0; k < HD; k++) s += xs[k] * Wf[(size_t)k * FC1D + c];
    z[m * FC1D + c] = fmaxf(s, 0.f);
}

__global__ void fc2_k(const float* __restrict__ z, const float* __restrict__ W,
                      const float* __restrict__ b, float* __restrict__ out) {
    int t = threadIdx.x;
    if (t >= BG * OUTD) return;
    int m = t / OUTD, c = t % OUTD;
    float s = b[c];
    #pragma unroll 4
    for (int k = 0; k < FC1D; k++) s += z[m * FC1D + k] * W[k * OUTD + c];
    out[t] = s;
}

// ---------------- launch ----------------
extern "C" void kernel_launch(void* const* d_in, const int* in_sizes, int n_in,
                              void* d_out, int out_size) {
    (void)in_sizes; (void)n_in; (void)out_size;
    float* FS = nullptr; int* IS = nullptr;
    __nv_bfloat16 *a1s = nullptr, *w1s = nullptr, *a2s = nullptr, *w2s = nullptr;
    cudaGetSymbolAddress((void**)&FS, d_fscratch);
    cudaGetSymbolAddress((void**)&IS, d_iscratch);
    cudaGetSymbolAddress((void**)&a1s, d_a1s);
    cudaGetSymbolAddress((void**)&w1s, d_w1s);
    cudaGetSymbolAddress((void**)&a2s, d_a2s);
    cudaGetSymbolAddress((void**)&w2s, d_w2s);
    cudaFuncSetAttribute(gemm_mma, cudaFuncAttributeMaxDynamicSharedMemorySize, GEMM_SMEM_DYN);

    const float* x   = (const float*)d_in[0];
    const int*   ei  = (const int*)d_in[1];
    const float* W1  = (const float*)d_in[3];
    const float* b1  = (const float*)d_in[4];
    const float* g1  = (const float*)d_in[5];
    const float* be1 = (const float*)d_in[6];
    const float* p1  = (const float*)d_in[7];
    const float* W2  = (const float*)d_in[8];
    const float* b2  = (const float*)d_in[9];
    const float* g2  = (const float*)d_in[10];
    const float* be2 = (const float*)d_in[11];
    const float* p2  = (const float*)d_in[12];
    const float* Wf  = (const float*)d_in[13];
    const float* bf  = (const float*)d_in[14];
    const float* Wf1 = (const float*)d_in[15];
    const float* bf1 = (const float*)d_in[16];
    float* out = (float*)d_out;

    const int* src = ei;
    const int* dst = ei + E_TOT;

    float* lin1  = FS + F_LIN1;
    float* agg1  = FS + F_AGG1;
    float* hp1   = FS + F_HP1;
    float* lin2  = FS + F_LIN2;
    float* agg2  = FS + F_AGG2;
    float* hp2   = FS + F_HP2;
    float* dinv1 = FS + F_DINV1;
    float* dinv2 = FS + F_DINV2;
    float* score1= FS + F_SCORE1;
    float* score2= FS + F_SCORE2;
    float* val1  = FS + F_VAL1;
    float* val2  = FS + F_VAL2;
    float* colsum= FS + F_COLSUM;
    float* colsq = FS + F_COLSQ;
    float* scale = FS + F_SCALE;
    float* shift = FS + F_SHIFT;
    float* pn    = FS + F_PN;
    float* x1    = FS + F_X1;
    float* x2    = FS + F_X2;
    float* z     = FS + F_Z;

    int* src2  = IS + I_SRC2;
    int* dst2  = IS + I_DST2;
    int* csr   = IS + I_CSR;
    int* cnt1  = IS + I_CNT1;
    int* off1  = IS + I_OFF1;
    int* cur1  = IS + I_CUR1;
    int* cnt2  = IS + I_CNT2;
    int* off2  = IS + I_OFF2;
    int* cur2  = IS + I_CUR2;
    int* perm1 = IS + I_PERM1;
    int* perm2 = IS + I_PERM2;
    int* newid = IS + I_NEWID;

    // ===== Layer 1 =====
    asplit_k<<<(int)(((size_t)N1 * F_IN) / 256), 256>>>(x, a1s, 9);
    wsplit_k<<<(F_IN * HD) / 256, 256>>>(W1, w1s, F_IN);
    gemm_mma<<<dim3(HD / 128, N1 / 128), 256, GEMM_SMEM_DYN>>>(a1s, w1s, lin1, 3 * F_IN);

    // CSR build (layer 1)
    zero_int_k<<<(N1 + 255) / 256, 256>>>(cnt1, N1);
    count_k<<<E_TOT / 256, 256>>>(src, dst, cnt1, E_TOT, 0);
    scan_off_k<NPG><<<BG, NPG>>>(cnt1, off1, cur1);
    fill_csr_k<<<E_TOT / 256, 256>>>(src, dst, cur1, csr, E_TOT, 0);
    dinv_from_cnt_k<<<(N1 + 255) / 256, 256>>>(cnt1, dinv1, N1);

    agg_gather_k<<<N1, 256>>>(lin1, csr, off1, cnt1, dinv1, b1, agg1);

    fill_k<<<(2 * HD + 255) / 256, 256>>>(colsum, 2 * HD, 0.f);
    colstats_k<<<dim3(HD / 256, 64), 256>>>(agg1, N1, colsum, colsq);
    bnprep_k<<<HD / 256, 256>>>(colsum, colsq, 1.0f / (float)N1, g1, be1, scale, shift);
    pnorm_k<<<1, HD>>>(p1, pn);
    bn_relu_score_k<<<N1, 256>>>(agg1, scale, shift, pn, score1);

    topk_k<NPG, KP1><<<BG, NPG>>>(score1, val1, perm1, newid);
    gather_split_k<<<N2, 256>>>(agg1, perm1, val1, hp1, a2s);   // fused asplit2
    remap_k<<<E_TOT / 256, 256>>>(src, dst, newid, src2, dst2, E_TOT);
    meanpool_k<<<dim3(BG, HD / 256), 256>>>(hp1, x1, KP1);

    // ===== Layer 2 =====
    wsplit_k<<<(HD * HD) / 256, 256>>>(W2, w2s, HD);
    gemm_mma<<<dim3(HD / 128, N2 / 128), 256, GEMM_SMEM_DYN>>>(a2s, w2s, lin2, 3 * HD);

    zero_int_k<<<(N2 + 255) / 256, 256>>>(cnt2, N2);
    count_k<<<E_TOT / 256, 256>>>(src2, dst2, cnt2, E_TOT, 1);
    scan_off_k<KP1><<<BG, KP1>>>(cnt2, off2, cur2);
    fill_csr_k<<<E_TOT / 256, 256>>>(src2, dst2, cur2, csr, E_TOT, 1);
    dinv_from_cnt_k<<<(N2 + 255) / 256, 256>>>(cnt2, dinv2, N2);

    agg_gather_k<<<N2, 256>>>(lin2, csr, off2, cnt2, dinv2, b2, agg2);

    fill_k<<<(2 * HD + 255) / 256, 256>>>(colsum, 2 * HD, 0.f);
    colstats_k<<<dim3(HD / 256, 32), 256>>>(agg2, N2, colsum, colsq);
    bnprep_k<<<HD / 256, 256>>>(colsum, colsq, 1.0f / (float)N2, g2, be2, scale, shift);
    pnorm_k<<<1, HD>>>(p2, pn);
    bn_relu_score_k<<<N2, 256>>>(agg2, scale, shift, pn, score2);

    topk_k<KP1, KP2><<<BG, KP1>>>(score2, val2, perm2, nullptr);
    gather_split_k<<<N3, 256>>>(agg2, perm2, val2, hp2, nullptr);
    meanpool_k<<<dim3(BG, HD / 256), 256>>>(hp2, x2, KP2);

    // ===== Head =====
    fc1_k<<<BG, FC1D>>>(x1, x2, Wf, bf, z);
    fc2_k<<<1, BG * OUTD>>>(z, Wf1, bf1, out);
}

// round 5
// speedup vs baseline: 2.4331x; 1.0963x over previous
#include <cuda_runtime.h>
#include <cuda_bf16.h>
#include <math.h>
#include <cstdint>

// ---------------- problem constants ----------------
#define BG     32
#define NPG    1024
#define DEGC   8
#define F_IN   512
#define HD     1024
#define OUTD   10
#define E_TOT  (BG*NPG*DEGC)   // 262144
#define EPG    (NPG*DEGC)      // 8192 edges per graph
#define N1     (BG*NPG)        // 32768
#define KP1    512
#define N2     (BG*KP1)        // 16384
#define KP2    256
#define N3     (BG*KP2)        // 8192
#define FC1D   512
#define BN_EPS 1e-5f

// ---------------- scratch layout (floats) ----------------
#define F_LIN1   ((size_t)0)
#define F_AGG1   (F_LIN1 + (size_t)N1*HD)
#define F_HP1    (F_AGG1 + (size_t)N1*HD)
#define F_LIN2   (F_HP1  + (size_t)N2*HD)
#define F_AGG2   (F_LIN2 + (size_t)N2*HD)
#define F_HP2    (F_AGG2 + (size_t)N2*HD)
#define F_DINV1  (F_HP2  + (size_t)N3*HD)
#define F_DINV2  (F_DINV1 + N1)
#define F_SCORE1 (F_DINV2 + N2)
#define F_SCORE2 (F_SCORE1 + N1)
#define F_VAL1   (F_SCORE2 + N2)
#define F_VAL2   (F_VAL1 + N2)
#define F_COLSUM (F_VAL2 + N3)
#define F_COLSQ  (F_COLSUM + HD)
#define F_SCALE  (F_COLSQ + HD)
#define F_SHIFT  (F_SCALE + HD)
#define F_PN     (F_SHIFT + HD)
#define F_X1     (F_PN + HD)
#define F_X2     (F_X1 + BG*HD)
#define F_Z      (F_X2 + BG*HD)
#define F_END    (F_Z + BG*FC1D)

#define I_SRC2   ((size_t)0)
#define I_DST2   (I_SRC2 + E_TOT)
#define I_CSR    (I_DST2 + E_TOT)
#define I_CNT1   (I_CSR + E_TOT)
#define I_OFF1   (I_CNT1 + N1)
#define I_CUR1   (I_OFF1 + N1)
#define I_CNT2   (I_CUR1 + N1)
#define I_OFF2   (I_CNT2 + N2)
#define I_CUR2   (I_OFF2 + N2)
#define I_PERM1  (I_CUR2 + N2)
#define I_PERM2  (I_PERM1 + N2)
#define I_NEWID  (I_PERM2 + N3)
#define I_END    (I_NEWID + N1)

__device__ float d_fscratch[F_END];
__device__ int   d_iscratch[I_END];

// bf16 split operands (A' = [hi|hi|lo], B' = [hi|lo|hi], B' stored [N][3K])
__device__ __nv_bfloat16 d_a1s[(size_t)N1 * 3 * F_IN];
__device__ __nv_bfloat16 d_w1s[(size_t)HD * 3 * F_IN];
__device__ __nv_bfloat16 d_a2s[(size_t)N2 * 3 * HD];
__device__ __nv_bfloat16 d_w2s[(size_t)HD * 3 * HD];

// ================= helpers =================
__device__ __forceinline__ uint32_t smem_u32(const void* p) {
    uint32_t a;
    asm("{ .reg .u64 t; cvta.to.shared.u64 t, %1; cvt.u32.u64 %0, t; }" : "=r"(a) : "l"(p));
    return a;
}
#define SWZ128(b) ((b) ^ (((b) >> 3) & 0x70))

__device__ __forceinline__ void cp16(uint32_t dst, const void* src) {
    asm volatile("cp.async.cg.shared.global [%0], [%1], 16;" :: "r"(dst), "l"(src));
}

#define LDSM4(r0, r1, r2, r3, addr) \
    asm volatile("ldmatrix.sync.aligned.m8n8.x4.shared.b16 {%0,%1,%2,%3}, [%4];" \
                 : "=r"(r0), "=r"(r1), "=r"(r2), "=r"(r3) : "r"(addr))

#define MMA16816(d, a, b0, b1) \
    asm volatile("mma.sync.aligned.m16n8k16.row.col.f32.bf16.bf16.f32 " \
                 "{%0,%1,%2,%3}, {%4,%5,%6,%7}, {%8,%9}, {%0,%1,%2,%3};" \
                 : "+f"((d)[0]), "+f"((d)[1]), "+f"((d)[2]), "+f"((d)[3]) \
                 : "r"((a)[0]), "r"((a)[1]), "r"((a)[2]), "r"((a)[3]), \
                   "r"(b0), "r"(b1))

// 3-stage ring: 3 * 32KB + 1KB alignment pad -> 2 CTAs/SM co-resident
#define GEMM_SMEM_DYN (3 * 32768 + 1024)

// ---- HMMA GEMM: C[M,1024] = A'[M,K3] x B'[1024,K3]^T (bf16 in, fp32 out)
// CTA tile 128x128, K-chunk 64, 3-stage cp.async ring, 2 CTAs/SM.
__global__ void __launch_bounds__(256, 2) gemm_mma(
    const __nv_bfloat16* __restrict__ A, const __nv_bfloat16* __restrict__ B,
    float* __restrict__ C, int K3)
{
    extern __shared__ char smem[];
    const uint32_t base = (smem_u32(smem) + 1023u) & ~1023u;
    const int tid = threadIdx.x, wid = tid >> 5, lane = tid & 31;
    const int m0 = blockIdx.y * 128;
    const int n0 = blockIdx.x * 128;
    const int wm = (wid & 3) * 32;
    const int wn = (wid >> 2) * 64;

    float acc[2][8][4];
    #pragma unroll
    for (int i = 0; i < 2; i++)
        #pragma unroll
        for (int j = 0; j < 8; j++)
            #pragma unroll
            for (int r = 0; r < 4; r++) acc[i][j][r] = 0.f;

    const int rA0 = (wm + (lane & 15)) * 128;
    const int cA  = (lane >> 4) * 16;
    const int rBb = (wn + ((lane >> 4) << 3) + (lane & 7)) * 128;
    const int cB  = ((lane >> 3) & 1) * 16;

    const int nStages = K3 >> 6;
    const __nv_bfloat16* Abase = A + (size_t)m0 * K3;
    const __nv_bfloat16* Bbase = B + (size_t)n0 * K3;
    const int lrow = tid >> 3, lc8 = tid & 7;

    // prologue: stages 0,1
    #pragma unroll
    for (int s = 0; s < 2; s++) {
        uint32_t dA = base + s * 32768, dB = dA + 16384;
        const __nv_bfloat16* Ab = Abase + s * 64;
        const __nv_bfloat16* Bb = Bbase + s * 64;
        #pragma unroll
        for (int i = 0; i < 4; i++) {
            int row = lrow + i * 32;
            cp16(dA + SWZ128(row * 128 + lc8 * 16), Ab + (size_t)row * K3 + lc8 * 8);
            cp16(dB + SWZ128(row * 128 + lc8 * 16), Bb + (size_t)row * K3 + lc8 * 8);
        }
        asm volatile("cp.async.commit_group;" ::: "memory");
    }

    int buf = 0;       // stage ks buffer index, cycles 0,1,2
    int pbuf = 2;      // prefetch buffer index = (ks+2)%3
    for (int ks = 0; ks < nStages; ks++) {
        asm volatile("cp.async.wait_group 1;" ::: "memory");   // stage ks ready
        __syncthreads();                                       // all warps done ks-1

        if (ks + 2 < nStages) {                                // prefetch ks+2
            uint32_t dA = base + pbuf * 32768, dB = dA + 16384;
            const __nv_bfloat16* Ab = Abase + (ks + 2) * 64;
            const __nv_bfloat16* Bb = Bbase + (ks + 2) * 64;
            #pragma unroll
            for (int i = 0; i < 4; i++) {
                int row = lrow + i * 32;
                cp16(dA + SWZ128(row * 128 + lc8 * 16), Ab + (size_t)row * K3 + lc8 * 8);
                cp16(dB + SWZ128(row * 128 + lc8 * 16), Bb + (size_t)row * K3 + lc8 * 8);
            }
        }
        asm volatile("cp.async.commit_group;" ::: "memory");   // uniform group count

        const uint32_t As = base + buf * 32768;
        const uint32_t Bs = As + 16384;
        #pragma unroll
        for (int kk = 0; kk < 4; kk++) {
            const int kb = kk * 32;
            uint32_t a0[4], a1[4];
            LDSM4(a0[0], a0[1], a0[2], a0[3], As + SWZ128(rA0 + cA + kb));
            LDSM4(a1[0], a1[1], a1[2], a1[3], As + SWZ128(rA0 + 16 * 128 + cA + kb));
            uint32_t bf[4][4];
            #pragma unroll
            for (int jj = 0; jj < 4; jj++)
                LDSM4(bf[jj][0], bf[jj][1], bf[jj][2], bf[jj][3],
                      Bs + SWZ128(rBb + jj * 16 * 128 + cB + kb));
            #pragma unroll
            for (int j = 0; j < 8; j++) {
                const int jj = j >> 1, hh = (j & 1) * 2;
                MMA16816(acc[0][j], a0, bf[jj][hh], bf[jj][hh + 1]);
                MMA16816(acc[1][j], a1, bf[jj][hh], bf[jj][hh + 1]);
            }
        }
        buf = (buf == 2) ? 0 : buf + 1;
        pbuf = (pbuf == 2) ? 0 : pbuf + 1;
    }

    const int rq = lane >> 2, cq = (lane & 3) * 2;
    #pragma unroll
    for (int mi = 0; mi < 2; mi++) {
        int rowb = m0 + wm + mi * 16 + rq;
        #pragma unroll
        for (int j = 0; j < 8; j++) {
            float* p0 = C + (size_t)rowb * HD + n0 + wn + j * 8 + cq;
            *(float2*)p0 = make_float2(acc[mi][j][0], acc[mi][j][1]);
            *(float2*)(p0 + 8 * (size_t)HD) = make_float2(acc[mi][j][2], acc[mi][j][3]);
        }
    }
}

// ---- bf16 split kernels ----
__global__ void asplit_k(const float* __restrict__ X, __nv_bfloat16* __restrict__ O, int kshift) {
    size_t i = (size_t)blockIdx.x * blockDim.x + threadIdx.x;
    const int K = 1 << kshift;
    size_t m = i >> kshift;
    int k = (int)(i & (K - 1));
    float v = X[i];
    __nv_bfloat16 hi = __float2bfloat16(v);
    __nv_bfloat16 lo = __float2bfloat16(v - __bfloat162float(hi));
    __nv_bfloat16* row = O + m * (size_t)(3 * K);
    row[k] = hi; row[K + k] = hi; row[2 * K + k] = lo;
}

__global__ void wsplit_k(const float* __restrict__ W, __nv_bfloat16* __restrict__ O, int K) {
    int i = blockIdx.x * blockDim.x + threadIdx.x;   // over K*1024
    int k = i >> 10, n = i & 1023;
    if (k >= K) return;
    float v = W[i];
    __nv_bfloat16 hi = __float2bfloat16(v);
    __nv_bfloat16 lo = __float2bfloat16(v - __bfloat162float(hi));
    size_t base = (size_t)n * (3 * K);
    O[base + k] = hi; O[base + K + k] = lo; O[base + 2 * K + k] = hi;
}

// ---------------- CSR build ----------------
__global__ void zero_int_k(int* p, int n) {
    int i = blockIdx.x * blockDim.x + threadIdx.x;
    if (i < n) p[i] = 0;
}

__global__ void count_k(const int* __restrict__ srcv, const int* __restrict__ dstv,
                        int* __restrict__ cnt, int n, int checkValid) {
    int e = blockIdx.x * blockDim.x + threadIdx.x;
    if (e >= n) return;
    if (checkValid && srcv[e] < 0) return;
    atomicAdd(&cnt[dstv[e]], 1);
}

// per-graph exclusive scan of counts -> offsets + cursor; also emits dinv
template<int NPGT>
__global__ void scan_off_k(const int* __restrict__ cnt, int* __restrict__ off,
                           int* __restrict__ cursor, float* __restrict__ dinv) {
    __shared__ int sh[NPGT];
    int b = blockIdx.x, t = threadIdx.x;
    int v = cnt[b * NPGT + t];
    sh[t] = v;
    dinv[b * NPGT + t] = rsqrtf(1.0f + (float)v);
    __syncthreads();
    #pragma unroll
    for (int d = 1; d < NPGT; d <<= 1) {
        int add = (t >= d) ? sh[t - d] : 0;
        __syncthreads();
        sh[t] += add;
        __syncthreads();
    }
    int o = b * EPG + sh[t] - v;
    off[b * NPGT + t] = o;
    cursor[b * NPGT + t] = o;
}

__global__ void fill_csr_k(const int* __restrict__ srcv, const int* __restrict__ dstv,
                           int* __restrict__ cursor, int* __restrict__ csr, int n, int checkValid) {
    int e = blockIdx.x * blockDim.x + threadIdx.x;
    if (e >= n) return;
    int s = srcv[e];
    if (checkValid && s < 0) return;
    int pos = atomicAdd(&cursor[dstv[e]], 1);
    csr[pos] = s;
}

// ---- CSR gather aggregation ----
__global__ void __launch_bounds__(256) agg_gather_k(
    const float* __restrict__ lin, const int* __restrict__ csr,
    const int* __restrict__ off, const int* __restrict__ cnt,
    const float* __restrict__ dinv, const float* __restrict__ bias,
    float* __restrict__ agg)
{
    const int n = blockIdx.x, t = threadIdx.x;
    const float iv = dinv[n];
    const int o = off[n], c = cnt[n];
    float4 b = ((const float4*)bias)[t];
    float4 l = ((const float4*)(lin + (size_t)n * HD))[t];
    const float iv2 = iv * iv;
    float4 acc = make_float4(fmaf(l.x, iv2, b.x), fmaf(l.y, iv2, b.y),
                             fmaf(l.z, iv2, b.z), fmaf(l.w, iv2, b.w));
    int j = 0;
    for (; j + 1 < c; j += 2) {
        int s0 = __ldg(&csr[o + j]), s1 = __ldg(&csr[o + j + 1]);
        float w0 = __ldg(&dinv[s0]) * iv, w1 = __ldg(&dinv[s1]) * iv;
        float4 v0 = ((const float4*)(lin + (size_t)s0 * HD))[t];
        float4 v1 = ((const float4*)(lin + (size_t)s1 * HD))[t];
        acc.x += v0.x * w0 + v1.x * w1;
        acc.y += v0.y * w0 + v1.y * w1;
        acc.z += v0.z * w0 + v1.z * w1;
        acc.w += v0.w * w0 + v1.w * w1;
    }
    if (j < c) {
        int s0 = __ldg(&csr[o + j]);
        float w0 = __ldg(&dinv[s0]) * iv;
        float4 v0 = ((const float4*)(lin + (size_t)s0 * HD))[t];
        acc.x += v0.x * w0; acc.y += v0.y * w0;
        acc.z += v0.z * w0; acc.w += v0.w * w0;
    }
    ((float4*)(agg + (size_t)n * HD))[t] = acc;
}

// ---------------- BN / score / pooling ----------------
__global__ void fill_k(float* p, int n, float v) {
    int i = blockIdx.x * blockDim.x + threadIdx.x;
    if (i < n) p[i] = v;
}

__global__ void colstats_k(const float* __restrict__ X, int nrows,
                           float* __restrict__ csum, float* __restrict__ csq) {
    int c = blockIdx.x * blockDim.x + threadIdx.x;
    int chunk = (nrows + gridDim.y - 1) / gridDim.y;
    int r0 = blockIdx.y * chunk;
    int r1 = min(r0 + chunk, nrows);
    float s = 0.f, q = 0.f;
    const float* p = X + (size_t)r0 * HD + c;
    for (int r = r0; r < r1; r++, p += HD) { float v = *p; s += v; q += v * v; }
    atomicAdd(&csum[c], s);
    atomicAdd(&csq[c], q);
}

__global__ void bnprep_k(const float* __restrict__ csum, const float* __restrict__ csq,
                         float invn, const float* __restrict__ g, const float* __restrict__ be,
                         float* __restrict__ scale, float* __restrict__ shift) {
    int c = blockIdx.x * blockDim.x + threadIdx.x;
    float m = csum[c] * invn;
    float v = csq[c] * invn - m * m;
    float rs = rsqrtf(v + BN_EPS) * g[c];
    scale[c] = rs;
    shift[c] = be[c] - m * rs;
}

__global__ void pnorm_k(const float* __restrict__ p, float* __restrict__ pn) {
    int t = threadIdx.x;
    float v = p[t];
    float s = v * v;
    #pragma unroll
    for (int o = 16; o > 0; o >>= 1) s += __shfl_down_sync(0xffffffff, s, o);
    __shared__ float red[32];
    if ((t & 31) == 0) red[t >> 5] = s;
    __syncthreads();
    if (t < 32) {
        float x = red[t];
        #pragma unroll
        for (int o = 16; o > 0; o >>= 1) x += __shfl_down_sync(0xffffffff, x, o);
        if (t == 0) red[0] = x;
    }
    __syncthreads();
    pn[t] = v * rsqrtf(red[0]);
}

__global__ void bn_relu_score_k(float* __restrict__ X, const float* __restrict__ scale,
                                const float* __restrict__ shift, const float* __restrict__ pn,
                                float* __restrict__ score) {
    int row = blockIdx.x, t = threadIdx.x;
    size_t base = (size_t)row * HD + t * 4;
    float4 v = *(float4*)&X[base];
    float4 sc = *(const float4*)&scale[t * 4];
    float4 sh = *(const float4*)&shift[t * 4];
    v.x = fmaxf(v.x * sc.x + sh.x, 0.f);
    v.y = fmaxf(v.y * sc.y + sh.y, 0.f);
    v.z = fmaxf(v.z * sc.z + sh.z, 0.f);
    v.w = fmaxf(v.w * sc.w + sh.w, 0.f);
    *(float4*)&X[base] = v;
    float4 p = *(const float4*)&pn[t * 4];
    float dot = v.x * p.x + v.y * p.y + v.z * p.z + v.w * p.w;
    #pragma unroll
    for (int o = 16; o > 0; o >>= 1) dot += __shfl_down_sync(0xffffffff, dot, o);
    __shared__ float red[8];
    if ((t & 31) == 0) red[t >> 5] = dot;
    __syncthreads();
    if (t == 0) {
        float s = 0.f;
        #pragma unroll
        for (int i = 0; i < 8; i++) s += red[i];
        score[row] = tanhf(s);
    }
}

template<int NPGT, int KK>
__global__ void topk_k(const float* __restrict__ score, float* __restrict__ val,
                       int* __restrict__ perm, int* __restrict__ newid) {
    __shared__ float s[NPGT];
    __shared__ int   id[NPGT];
    int b = blockIdx.x, t = threadIdx.x;
    s[t] = score[b * NPGT + t];
    id[t] = t;
    for (int size = 2; size <= NPGT; size <<= 1) {
        for (int stride = size >> 1; stride > 0; stride >>= 1) {
            __syncthreads();
            int j = t ^ stride;
            if (j > t) {
                float a = s[t], c = s[j];
                int ia = id[t], ic = id[j];
                bool aFirst = (a > c) || (a == c && ia < ic);
                bool descHere = ((t & size) == 0);
                if (descHere ? !aFirst : aFirst) {
                    s[t] = c; s[j] = a; id[t] = ic; id[j] = ia;
                }
            }
        }
    }
    __syncthreads();
    if (t < KK) {
        perm[b * KK + t] = b * NPGT + id[t];
        val[b * KK + t] = s[t];
        if (newid) newid[b * NPGT + id[t]] = b * KK + t;
    } else if (newid) {
        newid[b * NPGT + id[t]] = -1;
    }
}

__global__ void gather_split_k(const float* __restrict__ Hin, const int* __restrict__ perm,
                               const float* __restrict__ val, float* __restrict__ Hout,
                               __nv_bfloat16* __restrict__ As) {
    int row = blockIdx.x, t = threadIdx.x;
    int srow = perm[row];
    float v = val[row];
    float4 x = *(const float4*)&Hin[(size_t)srow * HD + t * 4];
    x.x *= v; x.y *= v; x.z *= v; x.w *= v;
    *(float4*)&Hout[(size_t)row * HD + t * 4] = x;
    if (As) {
        __nv_bfloat16* rp = As + (size_t)row * (3 * HD);
        int k = t * 4;
        float vs[4] = {x.x, x.y, x.z, x.w};
        #pragma unroll
        for (int i = 0; i < 4; i++) {
            __nv_bfloat16 hi = __float2bfloat16(vs[i]);
            __nv_bfloat16 lo = __float2bfloat16(vs[i] - __bfloat162float(hi));
            rp[k + i] = hi; rp[HD + k + i] = hi; rp[2 * HD + k + i] = lo;
        }
    }
}

__global__ void remap_k(const int* __restrict__ src, const int* __restrict__ dst,
                        const int* __restrict__ newid, int* __restrict__ src2,
                        int* __restrict__ dst2, int n) {
    int e = blockIdx.x * blockDim.x + threadIdx.x;
    if (e >= n) return;
    int s = newid[src[e]], d = newid[dst[e]];
    if (s < 0 || d < 0) { src2[e] = -1; dst2[e] = 0; }
    else { src2[e] = s; dst2[e] = d; }
}

__global__ void meanpool_k(const float* __restrict__ Hin, float* __restrict__ out, int kpg) {
    int b = blockIdx.x;
    int c = blockIdx.y * 256 + threadIdx.x;
    float sum = 0.f;
    const float* p = Hin + (size_t)b * kpg * HD + c;
    for (int r = 0; r < kpg; r++) sum += p[(size_t)r * HD];
    out[b * HD + c] = sum / (float)kpg;
}

__global__ void fc1_k(const float* __restrict__ x1, const float* __restrict__ x2,
                      const float* __restrict__ Wf, const float* __restrict__ bf,
                      float* __restrict__ z) {
    __shared__ float xs[HD];
    int m = blockIdx.x, c = threadIdx.x;
    xs[c]       = x1[m * HD + c]       + x2[m * HD + c];
    xs[c + 512] = x1[m * HD + c + 512] + x2[m * HD + c + 512];
    __syncthreads();
    float s = bf[c];
    #pragma unroll 4
    for (int k = 0; k < HD; k++) s += xs[k] * Wf[(size_t)k * FC1D + c];
    z[m * FC1D + c] = fmaxf(s, 0.f);
}

__global__ void fc2_k(const float* __restrict__ z, const float* __restrict__ W,
                      const float* __restrict__ b, float* __restrict__ out) {
    int t = threadIdx.x;
    if (t >= BG * OUTD) return;
    int m = t / OUTD, c = t % OUTD;
    float s = b[c];
    #pragma unroll 4
    for (int k = 0; k < FC1D; k++) s += z[m * FC1D + k] * W[k * OUTD + c];
    out[t] = s;
}

// ---------------- launch ----------------
extern "C" void kernel_launch(void* const* d_in, const int* in_sizes, int n_in,
                              void* d_out, int out_size) {
    (void)in_sizes; (void)n_in; (void)out_size;
    float* FS = nullptr; int* IS = nullptr;
    __nv_bfloat16 *a1s = nullptr, *w1s = nullptr, *a2s = nullptr, *w2s = nullptr;
    cudaGetSymbolAddress((void**)&FS, d_fscratch);
    cudaGetSymbolAddress((void**)&IS, d_iscratch);
    cudaGetSymbolAddress((void**)&a1s, d_a1s);
    cudaGetSymbolAddress((void**)&w1s, d_w1s);
    cudaGetSymbolAddress((void**)&a2s, d_a2s);
    cudaGetSymbolAddress((void**)&w2s, d_w2s);
    cudaFuncSetAttribute(gemm_mma, cudaFuncAttributeMaxDynamicSharedMemorySize, GEMM_SMEM_DYN);

    const float* x   = (const float*)d_in[0];
    const int*   ei  = (const int*)d_in[1];
    const float* W1  = (const float*)d_in[3];
    const float* b1  = (const float*)d_in[4];
    const float* g1  = (const float*)d_in[5];
    const float* be1 = (const float*)d_in[6];
    const float* p1  = (const float*)d_in[7];
    const float* W2  = (const float*)d_in[8];
    const float* b2  = (const float*)d_in[9];
    const float* g2  = (const float*)d_in[10];
    const float* be2 = (const float*)d_in[11];
    const float* p2  = (const float*)d_in[12];
    const float* Wf  = (const float*)d_in[13];
    const float* bf  = (const float*)d_in[14];
    const float* Wf1 = (const float*)d_in[15];
    const float* bf1 = (const float*)d_in[16];
    float* out = (float*)d_out;

    const int* src = ei;
    const int* dst = ei + E_TOT;

    float* lin1  = FS + F_LIN1;
    float* agg1  = FS + F_AGG1;
    float* hp1   = FS + F_HP1;
    float* lin2  = FS + F_LIN2;
    float* agg2  = FS + F_AGG2;
    float* hp2   = FS + F_HP2;
    float* dinv1 = FS + F_DINV1;
    float* dinv2 = FS + F_DINV2;
    float* score1= FS + F_SCORE1;
    float* score2= FS + F_SCORE2;
    float* val1  = FS + F_VAL1;
    float* val2  = FS + F_VAL2;
    float* colsum= FS + F_COLSUM;
    float* colsq = FS + F_COLSQ;
    float* scale = FS + F_SCALE;
    float* shift = FS + F_SHIFT;
    float* pn    = FS + F_PN;
    float* x1    = FS + F_X1;
    float* x2    = FS + F_X2;
    float* z     = FS + F_Z;

    int* src2  = IS + I_SRC2;
    int* dst2  = IS + I_DST2;
    int* csr   = IS + I_CSR;
    int* cnt1  = IS + I_CNT1;
    int* off1  = IS + I_OFF1;
    int* cur1  = IS + I_CUR1;
    int* cnt2  = IS + I_CNT2;
    int* off2  = IS + I_OFF2;
    int* cur2  = IS + I_CUR2;
    int* perm1 = IS + I_PERM1;
    int* perm2 = IS + I_PERM2;
    int* newid = IS + I_NEWID;

    // ===== Layer 1 =====
    asplit_k<<<(int)(((size_t)N1 * F_IN) / 256), 256>>>(x, a1s, 9);
    wsplit_k<<<(F_IN * HD) / 256, 256>>>(W1, w1s, F_IN);
    gemm_mma<<<dim3(HD / 128, N1 / 128), 256, GEMM_SMEM_DYN>>>(a1s, w1s, lin1, 3 * F_IN);

    zero_int_k<<<(N1 + 255) / 256, 256>>>(cnt1, N1);
    count_k<<<E_TOT / 256, 256>>>(src, dst, cnt1, E_TOT, 0);
    scan_off_k<NPG><<<BG, NPG>>>(cnt1, off1, cur1, dinv1);
    fill_csr_k<<<E_TOT / 256, 256>>>(src, dst, cur1, csr, E_TOT, 0);

    agg_gather_k<<<N1, 256>>>(lin1, csr, off1, cnt1, dinv1, b1, agg1);

    fill_k<<<(2 * HD + 255) / 256, 256>>>(colsum, 2 * HD, 0.f);
    colstats_k<<<dim3(HD / 256, 64), 256>>>(agg1, N1, colsum, colsq);
    bnprep_k<<<HD / 256, 256>>>(colsum, colsq, 1.0f / (float)N1, g1, be1, scale, shift);
    pnorm_k<<<1, HD>>>(p1, pn);
    bn_relu_score_k<<<N1, 256>>>(agg1, scale, shift, pn, score1);

    topk_k<NPG, KP1><<<BG, NPG>>>(score1, val1, perm1, newid);
    gather_split_k<<<N2, 256>>>(agg1, perm1, val1, hp1, a2s);
    remap_k<<<E_TOT / 256, 256>>>(src, dst, newid, src2, dst2, E_TOT);
    meanpool_k<<<dim3(BG, HD / 256), 256>>>(hp1, x1, KP1);

    // ===== Layer 2 =====
    wsplit_k<<<(HD * HD) / 256, 256>>>(W2, w2s, HD);
    gemm_mma<<<dim3(HD / 128, N2 / 128), 256, GEMM_SMEM_DYN>>>(a2s, w2s, lin2, 3 * HD);

    zero_int_k<<<(N2 + 255) / 256, 256>>>(cnt2, N2);
    count_k<<<E_TOT / 256, 256>>>(src2, dst2, cnt2, E_TOT, 1);
    scan_off_k<KP1><<<BG, KP1>>>(cnt2, off2, cur2, dinv2);
    fill_csr_k<<<E_TOT / 256, 256>>>(src2, dst2, cur2, csr, E_TOT, 1);

    agg_gather_k<<<N2, 256>>>(lin2, csr, off2, cnt2, dinv2, b2, agg2);

    fill_k<<<(2 * HD + 255) / 256, 256>>>(colsum, 2 * HD, 0.f);
    colstats_k<<<dim3(HD / 256, 32), 256>>>(agg2, N2, colsum, colsq);
    bnprep_k<<<HD / 256, 256>>>(colsum, colsq, 1.0f / (float)N2, g2, be2, scale, shift);
    pnorm_k<<<1, HD>>>(p2, pn);
    bn_relu_score_k<<<N2, 256>>>(agg2, scale, shift, pn, score2);

    topk_k<KP1, KP2><<<BG, KP1>>>(score2, val2, perm2, nullptr);
    gather_split_k<<<N3, 256>>>(agg2, perm2, val2, hp2, nullptr);
    meanpool_k<<<dim3(BG, HD / 256), 256>>>(hp2, x2, KP2);

    // ===== Head =====
    fc1_k<<<BG, FC1D>>>(x1, x2, Wf, bf, z);
    fc2_k<<<1, BG * OUTD>>>(z, Wf1, bf1, out);
}

// round 6
// speedup vs baseline: 2.5839x; 1.0620x over previous
#include <cuda_runtime.h>
#include <cuda_bf16.h>
#include <math.h>
#include <cstdint>

// ---------------- problem constants ----------------
#define BG     32
#define NPG    1024
#define DEGC   8
#define F_IN   512
#define HD     1024
#define OUTD   10
#define E_TOT  (BG*NPG*DEGC)   // 262144
#define EPG    (NPG*DEGC)      // 8192 edges per graph
#define N1     (BG*NPG)        // 32768
#define KP1    512
#define N2     (BG*KP1)        // 16384
#define KP2    256
#define N3     (BG*KP2)        // 8192
#define FC1D   512
#define BN_EPS 1e-5f

// ---------------- scratch layout (floats) ----------------
#define F_LIN1    ((size_t)0)
#define F_AGG1    (F_LIN1 + (size_t)N1*HD)
#define F_HP1     (F_AGG1 + (size_t)N1*HD)
#define F_LIN2    (F_HP1  + (size_t)N2*HD)
#define F_AGG2    (F_LIN2 + (size_t)N2*HD)
#define F_HP2     (F_AGG2 + (size_t)N2*HD)
#define F_DINV1   (F_HP2  + (size_t)N3*HD)
#define F_DINV2   (F_DINV1 + N1)
#define F_SCORE1  (F_DINV2 + N2)
#define F_SCORE2  (F_SCORE1 + N1)
#define F_VAL1    (F_SCORE2 + N2)
#define F_VAL2    (F_VAL1 + N2)
#define F_COLS    (F_VAL2 + N3)          // colsum1,colsq1,colsum2,colsq2 : 4*HD
#define F_SCALE   (F_COLS + 4*HD)
#define F_SHIFT   (F_SCALE + HD)
#define F_PN1     (F_SHIFT + HD)
#define F_PN2     (F_PN1 + HD)
#define F_X1      (F_PN2 + HD)
#define F_X2      (F_X1 + BG*HD)
#define F_Z       (F_X2 + BG*HD)
#define F_END     (F_Z + BG*FC1D)

#define I_SRC2   ((size_t)0)
#define I_DST2   (I_SRC2 + E_TOT)
#define I_CSR    (I_DST2 + E_TOT)
#define I_CNT1   (I_CSR + E_TOT)     // cnt1 then cnt2 contiguous
#define I_CNT2   (I_CNT1 + N1)
#define I_OFF1   (I_CNT2 + N2)
#define I_CUR1   (I_OFF1 + N1)
#define I_OFF2   (I_CUR1 + N1)
#define I_CUR2   (I_OFF2 + N2)
#define I_PERM1  (I_CUR2 + N2)
#define I_PERM2  (I_PERM1 + N2)
#define I_NEWID  (I_PERM2 + N3)
#define I_END    (I_NEWID + N1)

__device__ float d_fscratch[F_END];
__device__ int   d_iscratch[I_END];

// bf16 split operands (A' = [hi|hi|lo], B' = [hi|lo|hi], B' stored [N][3K])
__device__ __nv_bfloat16 d_a1s[(size_t)N1 * 3 * F_IN];
__device__ __nv_bfloat16 d_w1s[(size_t)HD * 3 * F_IN];
__device__ __nv_bfloat16 d_a2s[(size_t)N2 * 3 * HD];
__device__ __nv_bfloat16 d_w2s[(size_t)HD * 3 * HD];

// ================= helpers =================
__device__ __forceinline__ uint32_t smem_u32(const void* p) {
    uint32_t a;
    asm("{ .reg .u64 t; cvta.to.shared.u64 t, %1; cvt.u32.u64 %0, t; }" : "=r"(a) : "l"(p));
    return a;
}
#define SWZ128(b) ((b) ^ (((b) >> 3) & 0x70))

__device__ __forceinline__ void cp16(uint32_t dst, const void* src) {
    asm volatile("cp.async.cg.shared.global [%0], [%1], 16;" :: "r"(dst), "l"(src));
}

#define LDSM4(r0, r1, r2, r3, addr) \
    asm volatile("ldmatrix.sync.aligned.m8n8.x4.shared.b16 {%0,%1,%2,%3}, [%4];" \
                 : "=r"(r0), "=r"(r1), "=r"(r2), "=r"(r3) : "r"(addr))

#define MMA16816(d, a, b0, b1) \
    asm volatile("mma.sync.aligned.m16n8k16.row.col.f32.bf16.bf16.f32 " \
                 "{%0,%1,%2,%3}, {%4,%5,%6,%7}, {%8,%9}, {%0,%1,%2,%3};" \
                 : "+f"((d)[0]), "+f"((d)[1]), "+f"((d)[2]), "+f"((d)[3]) \
                 : "r"((a)[0]), "r"((a)[1]), "r"((a)[2]), "r"((a)[3]), \
                   "r"(b0), "r"(b1))

#define GEMM_SMEM_DYN (3 * 32768 + 1024)

// ---- HMMA GEMM: C[M,1024] = A'[M,K3] x B'[1024,K3]^T (bf16 in, fp32 out)
__global__ void __launch_bounds__(256, 2) gemm_mma(
    const __nv_bfloat16* __restrict__ A, const __nv_bfloat16* __restrict__ B,
    float* __restrict__ C, int K3)
{
    extern __shared__ char smem[];
    const uint32_t base = (smem_u32(smem) + 1023u) & ~1023u;
    const int tid = threadIdx.x, wid = tid >> 5, lane = tid & 31;
    const int m0 = blockIdx.y * 128;
    const int n0 = blockIdx.x * 128;
    const int wm = (wid & 3) * 32;
    const int wn = (wid >> 2) * 64;

    float acc[2][8][4];
    #pragma unroll
    for (int i = 0; i < 2; i++)
        #pragma unroll
        for (int j = 0; j < 8; j++)
            #pragma unroll
            for (int r = 0; r < 4; r++) acc[i][j][r] = 0.f;

    const int rA0 = (wm + (lane & 15)) * 128;
    const int cA  = (lane >> 4) * 16;
    const int rBb = (wn + ((lane >> 4) << 3) + (lane & 7)) * 128;
    const int cB  = ((lane >> 3) & 1) * 16;

    const int nStages = K3 >> 6;
    const __nv_bfloat16* Abase = A + (size_t)m0 * K3;
    const __nv_bfloat16* Bbase = B + (size_t)n0 * K3;
    const int lrow = tid >> 3, lc8 = tid & 7;

    #pragma unroll
    for (int s = 0; s < 2; s++) {
        uint32_t dA = base + s * 32768, dB = dA + 16384;
        const __nv_bfloat16* Ab = Abase + s * 64;
        const __nv_bfloat16* Bb = Bbase + s * 64;
        #pragma unroll
        for (int i = 0; i < 4; i++) {
            int row = lrow + i * 32;
            cp16(dA + SWZ128(row * 128 + lc8 * 16), Ab + (size_t)row * K3 + lc8 * 8);
            cp16(dB + SWZ128(row * 128 + lc8 * 16), Bb + (size_t)row * K3 + lc8 * 8);
        }
        asm volatile("cp.async.commit_group;" ::: "memory");
    }

    int buf = 0, pbuf = 2;
    for (int ks = 0; ks < nStages; ks++) {
        asm volatile("cp.async.wait_group 1;" ::: "memory");
        __syncthreads();

        if (ks + 2 < nStages) {
            uint32_t dA = base + pbuf * 32768, dB = dA + 16384;
            const __nv_bfloat16* Ab = Abase + (ks + 2) * 64;
            const __nv_bfloat16* Bb = Bbase + (ks + 2) * 64;
            #pragma unroll
            for (int i = 0; i < 4; i++) {
                int row = lrow + i * 32;
                cp16(dA + SWZ128(row * 128 + lc8 * 16), Ab + (size_t)row * K3 + lc8 * 8);
                cp16(dB + SWZ128(row * 128 + lc8 * 16), Bb + (size_t)row * K3 + lc8 * 8);
            }
        }
        asm volatile("cp.async.commit_group;" ::: "memory");

        const uint32_t As = base + buf * 32768;
        const uint32_t Bs = As + 16384;
        #pragma unroll
        for (int kk = 0; kk < 4; kk++) {
            const int kb = kk * 32;
            uint32_t a0[4], a1[4];
            LDSM4(a0[0], a0[1], a0[2], a0[3], As + SWZ128(rA0 + cA + kb));
            LDSM4(a1[0], a1[1], a1[2], a1[3], As + SWZ128(rA0 + 16 * 128 + cA + kb));
            uint32_t bf[4][4];
            #pragma unroll
            for (int jj = 0; jj < 4; jj++)
                LDSM4(bf[jj][0], bf[jj][1], bf[jj][2], bf[jj][3],
                      Bs + SWZ128(rBb + jj * 16 * 128 + cB + kb));
            #pragma unroll
            for (int j = 0; j < 8; j++) {
                const int jj = j >> 1, hh = (j & 1) * 2;
                MMA16816(acc[0][j], a0, bf[jj][hh], bf[jj][hh + 1]);
                MMA16816(acc[1][j], a1, bf[jj][hh], bf[jj][hh + 1]);
            }
        }
        buf = (buf == 2) ? 0 : buf + 1;
        pbuf = (pbuf == 2) ? 0 : pbuf + 1;
    }

    const int rq = lane >> 2, cq = (lane & 3) * 2;
    #pragma unroll
    for (int mi = 0; mi < 2; mi++) {
        int rowb = m0 + wm + mi * 16 + rq;
        #pragma unroll
        for (int j = 0; j < 8; j++) {
            float* p0 = C + (size_t)rowb * HD + n0 + wn + j * 8 + cq;
            *(float2*)p0 = make_float2(acc[mi][j][0], acc[mi][j][1]);
            *(float2*)(p0 + 8 * (size_t)HD) = make_float2(acc[mi][j][2], acc[mi][j][3]);
        }
    }
}

// ---- bf16 split kernels ----
__global__ void asplit_k(const float* __restrict__ X, __nv_bfloat16* __restrict__ O, int kshift) {
    size_t i = (size_t)blockIdx.x * blockDim.x + threadIdx.x;
    const int K = 1 << kshift;
    size_t m = i >> kshift;
    int k = (int)(i & (K - 1));
    float v = X[i];
    __nv_bfloat16 hi = __float2bfloat16(v);
    __nv_bfloat16 lo = __float2bfloat16(v - __bfloat162float(hi));
    __nv_bfloat16* row = O + m * (size_t)(3 * K);
    row[k] = hi; row[K + k] = hi; row[2 * K + k] = lo;
}

__global__ void wsplit_k(const float* __restrict__ W, __nv_bfloat16* __restrict__ O, int K) {
    int i = blockIdx.x * blockDim.x + threadIdx.x;
    int k = i >> 10, n = i & 1023;
    if (k >= K) return;
    float v = W[i];
    __nv_bfloat16 hi = __float2bfloat16(v);
    __nv_bfloat16 lo = __float2bfloat16(v - __bfloat162float(hi));
    size_t base = (size_t)n * (3 * K);
    O[base + k] = hi; O[base + K + k] = lo; O[base + 2 * K + k] = hi;
}

// ---------------- CSR build ----------------
__global__ void zero_int_k(int* p, int n) {
    int i = blockIdx.x * blockDim.x + threadIdx.x;
    if (i < n) p[i] = 0;
}

__global__ void count_k(const int* __restrict__ dstv, int* __restrict__ cnt, int n) {
    int e = blockIdx.x * blockDim.x + threadIdx.x;
    if (e < n) atomicAdd(&cnt[dstv[e]], 1);
}

// fused remap + count for layer 2
__global__ void remapcount_k(const int* __restrict__ src, const int* __restrict__ dst,
                             const int* __restrict__ newid, int* __restrict__ src2,
                             int* __restrict__ dst2, int* __restrict__ cnt2, int n) {
    int e = blockIdx.x * blockDim.x + threadIdx.x;
    if (e >= n) return;
    int s = newid[src[e]], d = newid[dst[e]];
    if (s < 0 || d < 0) { src2[e] = -1; dst2[e] = 0; }
    else { src2[e] = s; dst2[e] = d; atomicAdd(&cnt2[d], 1); }
}

template<int NPGT>
__global__ void scan_off_k(const int* __restrict__ cnt, int* __restrict__ off,
                           int* __restrict__ cursor, float* __restrict__ dinv) {
    __shared__ int sh[NPGT];
    int b = blockIdx.x, t = threadIdx.x;
    int v = cnt[b * NPGT + t];
    sh[t] = v;
    dinv[b * NPGT + t] = rsqrtf(1.0f + (float)v);
    __syncthreads();
    #pragma unroll
    for (int d = 1; d < NPGT; d <<= 1) {
        int add = (t >= d) ? sh[t - d] : 0;
        __syncthreads();
        sh[t] += add;
        __syncthreads();
    }
    int o = b * EPG + sh[t] - v;
    off[b * NPGT + t] = o;
    cursor[b * NPGT + t] = o;
}

__global__ void fill_csr_k(const int* __restrict__ srcv, const int* __restrict__ dstv,
                           int* __restrict__ cursor, int* __restrict__ csr, int n, int checkValid) {
    int e = blockIdx.x * blockDim.x + threadIdx.x;
    if (e >= n) return;
    int s = srcv[e];
    if (checkValid && s < 0) return;
    int pos = atomicAdd(&cursor[dstv[e]], 1);
    csr[pos] = s;
}

// ---- CSR gather aggregation ----
__global__ void __launch_bounds__(256) agg_gather_k(
    const float* __restrict__ lin, const int* __restrict__ csr,
    const int* __restrict__ off, const int* __restrict__ cnt,
    const float* __restrict__ dinv, const float* __restrict__ bias,
    float* __restrict__ agg)
{
    const int n = blockIdx.x, t = threadIdx.x;
    const float iv = dinv[n];
    const int o = off[n], c = cnt[n];
    float4 b = ((const float4*)bias)[t];
    float4 l = ((const float4*)(lin + (size_t)n * HD))[t];
    const float iv2 = iv * iv;
    float4 acc = make_float4(fmaf(l.x, iv2, b.x), fmaf(l.y, iv2, b.y),
                             fmaf(l.z, iv2, b.z), fmaf(l.w, iv2, b.w));
    int j = 0;
    for (; j + 1 < c; j += 2) {
        int s0 = __ldg(&csr[o + j]), s1 = __ldg(&csr[o + j + 1]);
        float w0 = __ldg(&dinv[s0]) * iv, w1 = __ldg(&dinv[s1]) * iv;
        float4 v0 = ((const float4*)(lin + (size_t)s0 * HD))[t];
        float4 v1 = ((const float4*)(lin + (size_t)s1 * HD))[t];
        acc.x += v0.x * w0 + v1.x * w1;
        acc.y += v0.y * w0 + v1.y * w1;
        acc.z += v0.z * w0 + v1.z * w1;
        acc.w += v0.w * w0 + v1.w * w1;
    }
    if (j < c) {
        int s0 = __ldg(&csr[o + j]);
        float w0 = __ldg(&dinv[s0]) * iv;
        float4 v0 = ((const float4*)(lin + (size_t)s0 * HD))[t];
        acc.x += v0.x * w0; acc.y += v0.y * w0;
        acc.z += v0.z * w0; acc.w += v0.w * w0;
    }
    ((float4*)(agg + (size_t)n * HD))[t] = acc;
}

// ---------------- BN / score / pooling ----------------
__global__ void fill_k(float* p, int n, float v) {
    int i = blockIdx.x * blockDim.x + threadIdx.x;
    if (i < n) p[i] = v;
}

__global__ void colstats_k(const float* __restrict__ X, int nrows,
                           float* __restrict__ csum, float* __restrict__ csq) {
    int c = blockIdx.x * blockDim.x + threadIdx.x;
    int chunk = (nrows + gridDim.y - 1) / gridDim.y;
    int r0 = blockIdx.y * chunk;
    int r1 = min(r0 + chunk, nrows);
    float s = 0.f, q = 0.f;
    const float* p = X + (size_t)r0 * HD + c;
    for (int r = r0; r < r1; r++, p += HD) { float v = *p; s += v; q += v * v; }
    atomicAdd(&csum[c], s);
    atomicAdd(&csq[c], q);
}

__global__ void bnprep_k(const float* __restrict__ csum, const float* __restrict__ csq,
                         float invn, const float* __restrict__ g, const float* __restrict__ be,
                         float* __restrict__ scale, float* __restrict__ shift) {
    int c = blockIdx.x * blockDim.x + threadIdx.x;
    float m = csum[c] * invn;
    float v = csq[c] * invn - m * m;
    float rs = rsqrtf(v + BN_EPS) * g[c];
    scale[c] = rs;
    shift[c] = be[c] - m * rs;
}

__global__ void pnorm_k(const float* __restrict__ p, float* __restrict__ pn) {
    int t = threadIdx.x;
    float v = p[t];
    float s = v * v;
    #pragma unroll
    for (int o = 16; o > 0; o >>= 1) s += __shfl_down_sync(0xffffffff, s, o);
    __shared__ float red[32];
    if ((t & 31) == 0) red[t >> 5] = s;
    __syncthreads();
    if (t < 32) {
        float x = red[t];
        #pragma unroll
        for (int o = 16; o > 0; o >>= 1) x += __shfl_down_sync(0xffffffff, x, o);
        if (t == 0) red[0] = x;
    }
    __syncthreads();
    pn[t] = v * rsqrtf(red[0]);
}

// score only (no writeback): score = tanh( relu(agg*sc+sh) . pn )
__global__ void score_k(const float* __restrict__ X, const float* __restrict__ scale,
                        const float* __restrict__ shift, const float* __restrict__ pn,
                        float* __restrict__ score) {
    int row = blockIdx.x, t = threadIdx.x;
    size_t base = (size_t)row * HD + t * 4;
    float4 v = *(const float4*)&X[base];
    float4 sc = *(const float4*)&scale[t * 4];
    float4 sh = *(const float4*)&shift[t * 4];
    v.x = fmaxf(fmaf(v.x, sc.x, sh.x), 0.f);
    v.y = fmaxf(fmaf(v.y, sc.y, sh.y), 0.f);
    v.z = fmaxf(fmaf(v.z, sc.z, sh.z), 0.f);
    v.w = fmaxf(fmaf(v.w, sc.w, sh.w), 0.f);
    float4 p = *(const float4*)&pn[t * 4];
    float dot = v.x * p.x + v.y * p.y + v.z * p.z + v.w * p.w;
    #pragma unroll
    for (int o = 16; o > 0; o >>= 1) dot += __shfl_down_sync(0xffffffff, dot, o);
    __shared__ float red[8];
    if ((t & 31) == 0) red[t >> 5] = dot;
    __syncthreads();
    if (t == 0) {
        float s = 0.f;
        #pragma unroll
        for (int i = 0; i < 8; i++) s += red[i];
        score[row] = tanhf(s);
    }
}

template<int NPGT, int KK>
__global__ void topk_k(const float* __restrict__ score, float* __restrict__ val,
                       int* __restrict__ perm, int* __restrict__ newid) {
    __shared__ float s[NPGT];
    __shared__ int   id[NPGT];
    int b = blockIdx.x, t = threadIdx.x;
    s[t] = score[b * NPGT + t];
    id[t] = t;
    for (int size = 2; size <= NPGT; size <<= 1) {
        for (int stride = size >> 1; stride > 0; stride >>= 1) {
            __syncthreads();
            int j = t ^ stride;
            if (j > t) {
                float a = s[t], c = s[j];
                int ia = id[t], ic = id[j];
                bool aFirst = (a > c) || (a == c && ia < ic);
                bool descHere = ((t & size) == 0);
                if (descHere ? !aFirst : aFirst) {
                    s[t] = c; s[j] = a; id[t] = ic; id[j] = ia;
                }
            }
        }
    }
    __syncthreads();
    if (t < KK) {
        perm[b * KK + t] = b * NPGT + id[t];
        val[b * KK + t] = s[t];
        if (newid) newid[b * NPGT + id[t]] = b * KK + t;
    } else if (newid) {
        newid[b * NPGT + id[t]] = -1;
    }
}

// lazy BN+ReLU gather: hp[row] = relu(agg[perm]*sc+sh) * val; optional bf16 split out
__global__ void gather_split_k(const float* __restrict__ Hin, const int* __restrict__ perm,
                               const float* __restrict__ val,
                               const float* __restrict__ scale, const float* __restrict__ shift,
                               float* __restrict__ Hout, __nv_bfloat16* __restrict__ As) {
    int row = blockIdx.x, t = threadIdx.x;
    int srow = perm[row];
    float v = val[row];
    float4 x = *(const float4*)&Hin[(size_t)srow * HD + t * 4];
    float4 sc = *(const float4*)&scale[t * 4];
    float4 sh = *(const float4*)&shift[t * 4];
    x.x = fmaxf(fmaf(x.x, sc.x, sh.x), 0.f) * v;
    x.y = fmaxf(fmaf(x.y, sc.y, sh.y), 0.f) * v;
    x.z = fmaxf(fmaf(x.z, sc.z, sh.z), 0.f) * v;
    x.w = fmaxf(fmaf(x.w, sc.w, sh.w), 0.f) * v;
    *(float4*)&Hout[(size_t)row * HD + t * 4] = x;
    if (As) {
        __nv_bfloat16* rp = As + (size_t)row * (3 * HD);
        int k = t * 4;
        float vs[4] = {x.x, x.y, x.z, x.w};
        #pragma unroll
        for (int i = 0; i < 4; i++) {
            __nv_bfloat16 hi = __float2bfloat16(vs[i]);
            __nv_bfloat16 lo = __float2bfloat16(vs[i] - __bfloat162float(hi));
            rp[k + i] = hi; rp[HD + k + i] = hi; rp[2 * HD + k + i] = lo;
        }
    }
}

__global__ void meanpool_k(const float* __restrict__ Hin, float* __restrict__ out, int kpg) {
    int b = blockIdx.x;
    int c = blockIdx.y * 256 + threadIdx.x;
    float sum = 0.f;
    const float* p = Hin + (size_t)b * kpg * HD + c;
    for (int r = 0; r < kpg; r++) sum += p[(size_t)r * HD];
    out[b * HD + c] = sum / (float)kpg;
}

__global__ void fc1_k(const float* __restrict__ x1, const float* __restrict__ x2,
                      const float* __restrict__ Wf, const float* __restrict__ bf,
                      float* __restrict__ z) {
    __shared__ float xs[HD];
    int m = blockIdx.x, c = threadIdx.x;
    xs[c]       = x1[m * HD + c]       + x2[m * HD + c];
    xs[c + 512] = x1[m * HD + c + 512] + x2[m * HD + c + 512];
    __syncthreads();
    float s = bf[c];
    #pragma unroll 4
    for (int k = 0; k < HD; k++) s += xs[k] * Wf[(size_t)k * FC1D + c];
    z[m * FC1D + c] = fmaxf(s, 0.f);
}

__global__ void fc2_k(const float* __restrict__ z, const float* __restrict__ W,
                      const float* __restrict__ b, float* __restrict__ out) {
    int t = threadIdx.x;
    if (t >= BG * OUTD) return;
    int m = t / OUTD, c = t % OUTD;
    float s = b[c];
    #pragma unroll 4
    for (int k = 0; k < FC1D; k++) s += z[m * FC1D + k] * W[k * OUTD + c];
    out[t] = s;
}

// ---------------- launch ----------------
extern "C" void kernel_launch(void* const* d_in, const int* in_sizes, int n_in,
                              void* d_out, int out_size) {
    (void)in_sizes; (void)n_in; (void)out_size;
    float* FS = nullptr; int* IS = nullptr;
    __nv_bfloat16 *a1s = nullptr, *w1s = nullptr, *a2s = nullptr, *w2s = nullptr;
    cudaGetSymbolAddress((void**)&FS, d_fscratch);
    cudaGetSymbolAddress((void**)&IS, d_iscratch);
    cudaGetSymbolAddress((void**)&a1s, d_a1s);
    cudaGetSymbolAddress((void**)&w1s, d_w1s);
    cudaGetSymbolAddress((void**)&a2s, d_a2s);
    cudaGetSymbolAddress((void**)&w2s, d_w2s);
    cudaFuncSetAttribute(gemm_mma, cudaFuncAttributeMaxDynamicSharedMemorySize, GEMM_SMEM_DYN);

    // side stream + events (created once; kernel_launch runs only for
    // correctness + one capture, never in the timed loop)
    static cudaStream_t sB = nullptr;
    static cudaEvent_t eF = nullptr, eB1 = nullptr, eT1 = nullptr, eG1 = nullptr, eB2 = nullptr;
    if (!sB) {
        cudaStreamCreateWithFlags(&sB, cudaStreamNonBlocking);
        cudaEventCreateWithFlags(&eF,  cudaEventDisableTiming);
        cudaEventCreateWithFlags(&eB1, cudaEventDisableTiming);
        cudaEventCreateWithFlags(&eT1, cudaEventDisableTiming);
        cudaEventCreateWithFlags(&eG1, cudaEventDisableTiming);
        cudaEventCreateWithFlags(&eB2, cudaEventDisableTiming);
    }

    const float* x   = (const float*)d_in[0];
    const int*   ei  = (const int*)d_in[1];
    const float* W1  = (const float*)d_in[3];
    const float* b1  = (const float*)d_in[4];
    const float* g1  = (const float*)d_in[5];
    const float* be1 = (const float*)d_in[6];
    const float* p1  = (const float*)d_in[7];
    const float* W2  = (const float*)d_in[8];
    const float* b2  = (const float*)d_in[9];
    const float* g2  = (const float*)d_in[10];
    const float* be2 = (const float*)d_in[11];
    const float* p2  = (const float*)d_in[12];
    const float* Wf  = (const float*)d_in[13];
    const float* bf  = (const float*)d_in[14];
    const float* Wf1 = (const float*)d_in[15];
    const float* bf1 = (const float*)d_in[16];
    float* out = (float*)d_out;

    const int* src = ei;
    const int* dst = ei + E_TOT;

    float* lin1  = FS + F_LIN1;
    float* agg1  = FS + F_AGG1;
    float* hp1   = FS + F_HP1;
    float* lin2  = FS + F_LIN2;
    float* agg2  = FS + F_AGG2;
    float* hp2   = FS + F_HP2;
    float* dinv1 = FS + F_DINV1;
    float* dinv2 = FS + F_DINV2;
    float* score1= FS + F_SCORE1;
    float* score2= FS + F_SCORE2;
    float* val1  = FS + F_VAL1;
    float* val2  = FS + F_VAL2;
    float* cols  = FS + F_COLS;              // [csum1|csq1|csum2|csq2]
    float* csum1 = cols, *csq1 = cols + HD, *csum2 = cols + 2 * HD, *csq2 = cols + 3 * HD;
    float* scale = FS + F_SCALE;
    float* shift = FS + F_SHIFT;
    float* pn1   = FS + F_PN1;
    float* pn2   = FS + F_PN2;
    float* x1    = FS + F_X1;
    float* x2    = FS + F_X2;
    float* z     = FS + F_Z;

    int* src2  = IS + I_SRC2;
    int* dst2  = IS + I_DST2;
    int* csr   = IS + I_CSR;
    int* cnt1  = IS + I_CNT1;   // cnt2 contiguous after
    int* cnt2  = IS + I_CNT2;
    int* off1  = IS + I_OFF1;
    int* cur1  = IS + I_CUR1;
    int* off2  = IS + I_OFF2;
    int* cur2  = IS + I_CUR2;
    int* perm1 = IS + I_PERM1;
    int* perm2 = IS + I_PERM2;
    int* newid = IS + I_NEWID;

    // ===== fork: side stream does CSR1 + weight split 2 + pnorms + zeroing =====
    cudaEventRecord(eF, 0);
    cudaStreamWaitEvent(sB, eF, 0);

    zero_int_k<<<(N1 + N2 + 255) / 256, 256, 0, sB>>>(cnt1, N1 + N2);
    fill_k<<<(4 * HD) / 256, 256, 0, sB>>>(cols, 4 * HD, 0.f);
    count_k<<<E_TOT / 256, 256, 0, sB>>>(dst, cnt1, E_TOT);
    scan_off_k<NPG><<<BG, NPG, 0, sB>>>(cnt1, off1, cur1, dinv1);
    fill_csr_k<<<E_TOT / 256, 256, 0, sB>>>(src, dst, cur1, csr, E_TOT, 0);
    wsplit_k<<<(HD * HD) / 256, 256, 0, sB>>>(W2, w2s, HD);
    pnorm_k<<<1, HD, 0, sB>>>(p1, pn1);
    pnorm_k<<<1, HD, 0, sB>>>(p2, pn2);
    cudaEventRecord(eB1, sB);

    // ===== main stream: layer-1 GEMM =====
    asplit_k<<<(int)(((size_t)N1 * F_IN) / 256), 256>>>(x, a1s, 9);
    wsplit_k<<<(F_IN * HD) / 256, 256>>>(W1, w1s, F_IN);
    gemm_mma<<<dim3(HD / 128, N1 / 128), 256, GEMM_SMEM_DYN>>>(a1s, w1s, lin1, 3 * F_IN);

    cudaStreamWaitEvent(0, eB1, 0);
    agg_gather_k<<<N1, 256>>>(lin1, csr, off1, cnt1, dinv1, b1, agg1);
    colstats_k<<<dim3(HD / 256, 64), 256>>>(agg1, N1, csum1, csq1);
    bnprep_k<<<HD / 256, 256>>>(csum1, csq1, 1.0f / (float)N1, g1, be1, scale, shift);
    score_k<<<N1, 256>>>(agg1, scale, shift, pn1, score1);
    topk_k<NPG, KP1><<<BG, NPG>>>(score1, val1, perm1, newid);
    cudaEventRecord(eT1, 0);

    // side stream: CSR for layer 2 while main does gather + GEMM2
    cudaStreamWaitEvent(sB, eT1, 0);
    remapcount_k<<<E_TOT / 256, 256, 0, sB>>>(src, dst, newid, src2, dst2, cnt2, E_TOT);
    scan_off_k<KP1><<<BG, KP1, 0, sB>>>(cnt2, off2, cur2, dinv2);
    fill_csr_k<<<E_TOT / 256, 256, 0, sB>>>(src2, dst2, cur2, csr, E_TOT, 1);

    gather_split_k<<<N2, 256>>>(agg1, perm1, val1, scale, shift, hp1, a2s);
    cudaEventRecord(eG1, 0);
    // meanpool1 on side stream (needs hp1)
    cudaStreamWaitEvent(sB, eG1, 0);
    meanpool_k<<<dim3(BG, HD / 256), 256, 0, sB>>>(hp1, x1, KP1);
    cudaEventRecord(eB2, sB);

    gemm_mma<<<dim3(HD / 128, N2 / 128), 256, GEMM_SMEM_DYN>>>(a2s, w2s, lin2, 3 * HD);

    cudaStreamWaitEvent(0, eB2, 0);
    agg_gather_k<<<N2, 256>>>(lin2, csr, off2, cnt2, dinv2, b2, agg2);
    colstats_k<<<dim3(HD / 256, 32), 256>>>(agg2, N2, csum2, csq2);
    bnprep_k<<<HD / 256, 256>>>(csum2, csq2, 1.0f / (float)N2, g2, be2, scale, shift);
    score_k<<<N2, 256>>>(agg2, scale, shift, pn2, score2);
    topk_k<KP1, KP2><<<BG, KP1>>>(score2, val2, perm2, nullptr);
    gather_split_k<<<N3, 256>>>(agg2, perm2, val2, scale, shift, hp2, nullptr);
    meanpool_k<<<dim3(BG, HD / 256), 256>>>(hp2, x2, KP2);

    // ===== Head =====
    fc1_k<<<BG, FC1D>>>(x1, x2, Wf, bf, z);
    fc2_k<<<1, BG * OUTD>>>(z, Wf1, bf1, out);
}